// round 11
// baseline (speedup 1.0000x reference)
#include <cuda_runtime.h>
#include <cuda_bf16.h>

// Problem constants
#define BATCH   4
#define SEQ     2048
#define DMODEL  1024
#define NHEADS  16
#define HDIM    64
#define MROWS   (BATCH * SEQ)          // 8192
#define ELEMS   (MROWS * DMODEL)       // 8388608

// Scratch: Q, K, V, heads  (row-major [M, D]; D index = h*64 + hd)
__device__ float g_q[ELEMS];
__device__ float g_k[ELEMS];
__device__ float g_v[ELEMS];
__device__ float g_h[ELEMS];

// ---------------------------------------------------------------------------
// SGEMM + bias: C[M,1024] = A[M,1024] * B[1024,1024] + bias
// 128x128 block tile, BK=8, 256 threads, 8x8 per-thread microtile.
// ---------------------------------------------------------------------------
__global__ __launch_bounds__(256, 2)
void sgemm_bias_kernel(const float* __restrict__ A, const float* __restrict__ B,
                       const float* __restrict__ bias, float* __restrict__ C)
{
    const int K = 1024, N = 1024;
    __shared__ float As[8 * 128];   // As[k][m]
    __shared__ float Bs[8 * 128];   // Bs[k][n]

    const int t  = threadIdx.x;
    const int bm = blockIdx.y * 128;
    const int bn = blockIdx.x * 128;

    const int arow = t >> 1;          // 0..127
    const int acol = (t & 1) << 2;    // 0 or 4
    const int brow = t >> 5;          // 0..7
    const int bcol = (t & 31) << 2;   // 0..124
    const int ty = t >> 4, tx = t & 15;

    float acc[8][8];
#pragma unroll
    for (int i = 0; i < 8; i++)
#pragma unroll
        for (int j = 0; j < 8; j++) acc[i][j] = 0.f;

    const float* Aptr = A + (bm + arow) * K + acol;
    const float* Bptr = B + brow * N + bn + bcol;

    for (int k0 = 0; k0 < K; k0 += 8) {
        float4 a = *(const float4*)(Aptr + k0);
        float4 b = *(const float4*)(Bptr + k0 * N);
        __syncthreads();
        As[(acol + 0) * 128 + arow] = a.x;
        As[(acol + 1) * 128 + arow] = a.y;
        As[(acol + 2) * 128 + arow] = a.z;
        As[(acol + 3) * 128 + arow] = a.w;
        *(float4*)&Bs[brow * 128 + bcol] = b;
        __syncthreads();
#pragma unroll
        for (int kk = 0; kk < 8; kk++) {
            float4 a0 = *(float4*)&As[kk * 128 + ty * 8];
            float4 a1 = *(float4*)&As[kk * 128 + ty * 8 + 4];
            float4 b0 = *(float4*)&Bs[kk * 128 + tx * 8];
            float4 b1 = *(float4*)&Bs[kk * 128 + tx * 8 + 4];
            float ar[8] = {a0.x, a0.y, a0.z, a0.w, a1.x, a1.y, a1.z, a1.w};
            float br[8] = {b0.x, b0.y, b0.z, b0.w, b1.x, b1.y, b1.z, b1.w};
#pragma unroll
            for (int i = 0; i < 8; i++)
#pragma unroll
                for (int j = 0; j < 8; j++)
                    acc[i][j] = fmaf(ar[i], br[j], acc[i][j]);
        }
    }

#pragma unroll
    for (int i = 0; i < 8; i++) {
        int row = bm + ty * 8 + i;
#pragma unroll
        for (int j0 = 0; j0 < 8; j0 += 4) {
            int col = bn + tx * 8 + j0;
            float4 c;
            c.x = acc[i][j0 + 0] + bias[col + 0];
            c.y = acc[i][j0 + 1] + bias[col + 1];
            c.z = acc[i][j0 + 2] + bias[col + 2];
            c.w = acc[i][j0 + 3] + bias[col + 3];
            *(float4*)&C[row * N + col] = c;
        }
    }
}

// ---------------------------------------------------------------------------
// Flash attention: one block handles (b,h) and 64 query rows.
// Br = Bc = 64, Hd = 64. Online softmax, O accumulated in registers.
// Smem (dynamic, 68608 B):
//   Qt[64 d][68] transposed Q tile (stride 68: 16B-aligned + bank rotation)
//   Kt[64 d][68] transposed K tile
//   Vs[64 k][64 c]
//   Ss[64 r][65]  scores/probs (pad 65 -> conflict-free row scans)
//   m_s/l_s/al_s[64] row stats
// ---------------------------------------------------------------------------
#define QT_STRIDE 68
#define FLASH_SMEM_FLOATS (64*QT_STRIDE*2 + 64*64 + 64*65 + 3*64)
#define FLASH_SMEM_BYTES  (FLASH_SMEM_FLOATS * 4)

__global__ __launch_bounds__(256, 2)
void flash_attn_kernel(const float* __restrict__ Q, const float* __restrict__ Kg,
                       const float* __restrict__ Vg, float* __restrict__ O)
{
    extern __shared__ float sm[];
    float* Qt   = sm;                        // 64*68
    float* Kt   = Qt + 64 * QT_STRIDE;       // 64*68
    float* Vs   = Kt + 64 * QT_STRIDE;       // 64*64
    float* Ss   = Vs + 64 * 64;              // 64*65
    float* m_s  = Ss + 64 * 65;
    float* l_s  = m_s + 64;
    float* al_s = l_s + 64;

    const int t  = threadIdx.x;
    const int qb = blockIdx.x * 64;
    const int bh = blockIdx.y;               // b*16 + h
    const int b  = bh >> 4;
    const int h  = bh & 15;
    const float scale = 0.125f;              // 1/sqrt(64)

    const int tx = t & 15, ty = t >> 4;
    const int iq0 = tx * 4, jk0 = ty * 4;    // QK^T microtile
    const int r0  = ty * 4, c0  = tx * 4;    // PV / O microtile

    // Load Q tile transposed: Qt[d][i]
    const float* Qbase = Q + (b * SEQ + qb) * DMODEL + h * HDIM;
    for (int e = t * 4; e < 64 * 64; e += 1024) {
        int i = e >> 6, d = e & 63;
        float4 v = *(const float4*)&Qbase[i * DMODEL + d];
        Qt[(d + 0) * QT_STRIDE + i] = v.x;
        Qt[(d + 1) * QT_STRIDE + i] = v.y;
        Qt[(d + 2) * QT_STRIDE + i] = v.z;
        Qt[(d + 3) * QT_STRIDE + i] = v.w;
    }
    if (t < 64) { m_s[t] = -1e30f; l_s[t] = 0.f; }

    float o[4][4];
#pragma unroll
    for (int i = 0; i < 4; i++)
#pragma unroll
        for (int j = 0; j < 4; j++) o[i][j] = 0.f;

    for (int kb = 0; kb < SEQ; kb += 64) {
        __syncthreads();   // previous tile's Ss/Vs reads complete

        // Load K (transposed) and V tiles
        const float* Kbase = Kg + (b * SEQ + kb) * DMODEL + h * HDIM;
        const float* Vbase = Vg + (b * SEQ + kb) * DMODEL + h * HDIM;
        for (int e = t * 4; e < 64 * 64; e += 1024) {
            int j = e >> 6, d = e & 63;
            float4 v = *(const float4*)&Kbase[j * DMODEL + d];
            Kt[(d + 0) * QT_STRIDE + j] = v.x;
            Kt[(d + 1) * QT_STRIDE + j] = v.y;
            Kt[(d + 2) * QT_STRIDE + j] = v.z;
            Kt[(d + 3) * QT_STRIDE + j] = v.w;
            float4 w = *(const float4*)&Vbase[j * DMODEL + d];
            *(float4*)&Vs[j * 64 + d] = w;
        }
        __syncthreads();

        // S = Q * K^T (scaled), microtile 4x4 per thread
        float s[4][4];
#pragma unroll
        for (int i = 0; i < 4; i++)
#pragma unroll
            for (int j = 0; j < 4; j++) s[i][j] = 0.f;
#pragma unroll 8
        for (int d = 0; d < 64; d++) {
            float4 qv = *(float4*)&Qt[d * QT_STRIDE + iq0];
            float4 kv = *(float4*)&Kt[d * QT_STRIDE + jk0];
            float qa[4] = {qv.x, qv.y, qv.z, qv.w};
            float ka[4] = {kv.x, kv.y, kv.z, kv.w};
#pragma unroll
            for (int i = 0; i < 4; i++)
#pragma unroll
                for (int j = 0; j < 4; j++)
                    s[i][j] = fmaf(qa[i], ka[j], s[i][j]);
        }
#pragma unroll
        for (int i = 0; i < 4; i++)
#pragma unroll
            for (int j = 0; j < 4; j++)
                Ss[(iq0 + i) * 65 + jk0 + j] = s[i][j] * scale;
        __syncthreads();

        // Online softmax: one thread per row (pad-65 => conflict-free scan)
        if (t < 64) {
            float* row = Ss + t * 65;
            float mo = m_s[t], mn = mo;
#pragma unroll 8
            for (int j = 0; j < 64; j++) mn = fmaxf(mn, row[j]);
            float al = __expf(mo - mn);
            float ls = 0.f;
#pragma unroll 8
            for (int j = 0; j < 64; j++) {
                float p = __expf(row[j] - mn);
                row[j] = p;
                ls += p;
            }
            m_s[t]  = mn;
            l_s[t]  = l_s[t] * al + ls;
            al_s[t] = al;
        }
        __syncthreads();

        // Rescale O, then O += P * V
#pragma unroll
        for (int i = 0; i < 4; i++) {
            float al = al_s[r0 + i];
            o[i][0] *= al; o[i][1] *= al; o[i][2] *= al; o[i][3] *= al;
        }
#pragma unroll 8
        for (int k = 0; k < 64; k++) {
            float4 vv = *(float4*)&Vs[k * 64 + c0];
#pragma unroll
            for (int i = 0; i < 4; i++) {
                float p = Ss[(r0 + i) * 65 + k];
                o[i][0] = fmaf(p, vv.x, o[i][0]);
                o[i][1] = fmaf(p, vv.y, o[i][1]);
                o[i][2] = fmaf(p, vv.z, o[i][2]);
                o[i][3] = fmaf(p, vv.w, o[i][3]);
            }
        }
    }

    // Epilogue: normalize by l and store heads in [B,S,H*Hd] row-major
    float* Obase = O + (b * SEQ + qb) * DMODEL + h * HDIM;
#pragma unroll
    for (int i = 0; i < 4; i++) {
        float inv = 1.f / l_s[r0 + i];
        float4 out;
        out.x = o[i][0] * inv;
        out.y = o[i][1] * inv;
        out.z = o[i][2] * inv;
        out.w = o[i][3] * inv;
        *(float4*)&Obase[(r0 + i) * DMODEL + c0] = out;
    }
}

// ---------------------------------------------------------------------------
extern "C" void kernel_launch(void* const* d_in, const int* in_sizes, int n_in,
                              void* d_out, int out_size)
{
    (void)in_sizes; (void)n_in; (void)out_size;
    const float* x  = (const float*)d_in[0];
    const float* Wq = (const float*)d_in[1];
    const float* bq = (const float*)d_in[2];
    const float* Wk = (const float*)d_in[3];
    const float* bk = (const float*)d_in[4];
    const float* Wv = (const float*)d_in[5];
    const float* bv = (const float*)d_in[6];
    const float* Wo = (const float*)d_in[7];
    const float* bo = (const float*)d_in[8];
    float* out = (float*)d_out;

    float *gq, *gk, *gv, *gh;
    cudaGetSymbolAddress((void**)&gq, g_q);
    cudaGetSymbolAddress((void**)&gk, g_k);
    cudaGetSymbolAddress((void**)&gv, g_v);
    cudaGetSymbolAddress((void**)&gh, g_h);

    dim3 ggrid(DMODEL / 128, MROWS / 128);   // (8, 64)
    sgemm_bias_kernel<<<ggrid, 256>>>(x, Wq, bq, gq);
    sgemm_bias_kernel<<<ggrid, 256>>>(x, Wk, bk, gk);
    sgemm_bias_kernel<<<ggrid, 256>>>(x, Wv, bv, gv);

    cudaFuncSetAttribute(flash_attn_kernel,
                         cudaFuncAttributeMaxDynamicSharedMemorySize,
                         FLASH_SMEM_BYTES);
    flash_attn_kernel<<<dim3(SEQ / 64, BATCH * NHEADS), 256, FLASH_SMEM_BYTES>>>(
        gq, gk, gv, gh);

    sgemm_bias_kernel<<<ggrid, 256>>>(gh, Wo, bo, out);
}

// round 12
// speedup vs baseline: 1.6016x; 1.6016x over previous
#include <cuda_runtime.h>
#include <cuda_bf16.h>

// Problem constants
#define BATCH   4
#define SEQ     2048
#define DMODEL  1024
#define NHEADS  16
#define HDIM    64
#define MROWS   (BATCH * SEQ)          // 8192
#define ELEMS   (MROWS * DMODEL)       // 8388608

// Scratch: Q, K, V, heads  (row-major [M, D]; D index = h*64 + hd)
__device__ float g_q[ELEMS];
__device__ float g_k[ELEMS];
__device__ float g_v[ELEMS];
__device__ float g_h[ELEMS];

// ---------------------------------------------------------------------------
// SGEMM + bias: C[M,1024] = A[M,1024] * B[1024,1024] + bias
// 128x128 block tile, BK=8, 256 threads, 8x8 per-thread microtile.
// ---------------------------------------------------------------------------
__global__ __launch_bounds__(256, 2)
void sgemm_bias_kernel(const float* __restrict__ A, const float* __restrict__ B,
                       const float* __restrict__ bias, float* __restrict__ C)
{
    const int K = 1024, N = 1024;
    __shared__ float As[8 * 128];   // As[k][m]
    __shared__ float Bs[8 * 128];   // Bs[k][n]

    const int t  = threadIdx.x;
    const int bm = blockIdx.y * 128;
    const int bn = blockIdx.x * 128;

    const int arow = t >> 1;          // 0..127
    const int acol = (t & 1) << 2;    // 0 or 4
    const int brow = t >> 5;          // 0..7
    const int bcol = (t & 31) << 2;   // 0..124
    const int ty = t >> 4, tx = t & 15;

    float acc[8][8];
#pragma unroll
    for (int i = 0; i < 8; i++)
#pragma unroll
        for (int j = 0; j < 8; j++) acc[i][j] = 0.f;

    const float* Aptr = A + (bm + arow) * K + acol;
    const float* Bptr = B + brow * N + bn + bcol;

    for (int k0 = 0; k0 < K; k0 += 8) {
        float4 a = *(const float4*)(Aptr + k0);
        float4 b = *(const float4*)(Bptr + k0 * N);
        __syncthreads();
        As[(acol + 0) * 128 + arow] = a.x;
        As[(acol + 1) * 128 + arow] = a.y;
        As[(acol + 2) * 128 + arow] = a.z;
        As[(acol + 3) * 128 + arow] = a.w;
        *(float4*)&Bs[brow * 128 + bcol] = b;
        __syncthreads();
#pragma unroll
        for (int kk = 0; kk < 8; kk++) {
            float4 a0 = *(float4*)&As[kk * 128 + ty * 8];
            float4 a1 = *(float4*)&As[kk * 128 + ty * 8 + 4];
            float4 b0 = *(float4*)&Bs[kk * 128 + tx * 8];
            float4 b1 = *(float4*)&Bs[kk * 128 + tx * 8 + 4];
            float ar[8] = {a0.x, a0.y, a0.z, a0.w, a1.x, a1.y, a1.z, a1.w};
            float br[8] = {b0.x, b0.y, b0.z, b0.w, b1.x, b1.y, b1.z, b1.w};
#pragma unroll
            for (int i = 0; i < 8; i++)
#pragma unroll
                for (int j = 0; j < 8; j++)
                    acc[i][j] = fmaf(ar[i], br[j], acc[i][j]);
        }
    }

#pragma unroll
    for (int i = 0; i < 8; i++) {
        int row = bm + ty * 8 + i;
#pragma unroll
        for (int j0 = 0; j0 < 8; j0 += 4) {
            int col = bn + tx * 8 + j0;
            float4 c;
            c.x = acc[i][j0 + 0] + bias[col + 0];
            c.y = acc[i][j0 + 1] + bias[col + 1];
            c.z = acc[i][j0 + 2] + bias[col + 2];
            c.w = acc[i][j0 + 3] + bias[col + 3];
            *(float4*)&C[row * N + col] = c;
        }
    }
}

// ---------------------------------------------------------------------------
// Flash attention: one block handles (b,h) and 64 query rows.
// Br = Bc = 64, Hd = 64. Online softmax, O accumulated in registers.
// Smem (dynamic, 68608 B):
//   Qt[64 d][68] transposed Q tile (stride 68: 16B-aligned + bank rotation)
//   Kt[64 d][68] transposed K tile
//   Vs[64 k][64 c]
//   Ss[64 r][65]  scores/probs (pad 65 -> conflict-free row scans)
//   m_s/l_s/al_s[64] row stats
// ---------------------------------------------------------------------------
#define QT_STRIDE 68
#define FLASH_SMEM_FLOATS (64*QT_STRIDE*2 + 64*64 + 64*65 + 3*64)
#define FLASH_SMEM_BYTES  (FLASH_SMEM_FLOATS * 4)

__global__ __launch_bounds__(256, 2)
void flash_attn_kernel(const float* __restrict__ Q, const float* __restrict__ Kg,
                       const float* __restrict__ Vg, float* __restrict__ O)
{
    extern __shared__ float sm[];
    float* Qt   = sm;                        // 64*68
    float* Kt   = Qt + 64 * QT_STRIDE;       // 64*68
    float* Vs   = Kt + 64 * QT_STRIDE;       // 64*64
    float* Ss   = Vs + 64 * 64;              // 64*65
    float* m_s  = Ss + 64 * 65;
    float* l_s  = m_s + 64;
    float* al_s = l_s + 64;

    const int t  = threadIdx.x;
    const int qb = blockIdx.x * 64;
    const int bh = blockIdx.y;               // b*16 + h
    const int b  = bh >> 4;
    const int h  = bh & 15;
    const float scale = 0.125f;              // 1/sqrt(64)

    const int tx = t & 15, ty = t >> 4;
    const int iq0 = tx * 4, jk0 = ty * 4;    // QK^T microtile
    const int r0  = ty * 4, c0  = tx * 4;    // PV / O microtile

    // Load Q tile transposed: Qt[d][i]
    const float* Qbase = Q + (b * SEQ + qb) * DMODEL + h * HDIM;
    for (int e = t * 4; e < 64 * 64; e += 1024) {
        int i = e >> 6, d = e & 63;
        float4 v = *(const float4*)&Qbase[i * DMODEL + d];
        Qt[(d + 0) * QT_STRIDE + i] = v.x;
        Qt[(d + 1) * QT_STRIDE + i] = v.y;
        Qt[(d + 2) * QT_STRIDE + i] = v.z;
        Qt[(d + 3) * QT_STRIDE + i] = v.w;
    }
    if (t < 64) { m_s[t] = -1e30f; l_s[t] = 0.f; }

    float o[4][4];
#pragma unroll
    for (int i = 0; i < 4; i++)
#pragma unroll
        for (int j = 0; j < 4; j++) o[i][j] = 0.f;

    for (int kb = 0; kb < SEQ; kb += 64) {
        __syncthreads();   // previous tile's Ss/Vs reads complete

        // Load K (transposed) and V tiles
        const float* Kbase = Kg + (b * SEQ + kb) * DMODEL + h * HDIM;
        const float* Vbase = Vg + (b * SEQ + kb) * DMODEL + h * HDIM;
        for (int e = t * 4; e < 64 * 64; e += 1024) {
            int j = e >> 6, d = e & 63;
            float4 v = *(const float4*)&Kbase[j * DMODEL + d];
            Kt[(d + 0) * QT_STRIDE + j] = v.x;
            Kt[(d + 1) * QT_STRIDE + j] = v.y;
            Kt[(d + 2) * QT_STRIDE + j] = v.z;
            Kt[(d + 3) * QT_STRIDE + j] = v.w;
            float4 w = *(const float4*)&Vbase[j * DMODEL + d];
            *(float4*)&Vs[j * 64 + d] = w;
        }
        __syncthreads();

        // S = Q * K^T (scaled), microtile 4x4 per thread
        float s[4][4];
#pragma unroll
        for (int i = 0; i < 4; i++)
#pragma unroll
            for (int j = 0; j < 4; j++) s[i][j] = 0.f;
#pragma unroll 8
        for (int d = 0; d < 64; d++) {
            float4 qv = *(float4*)&Qt[d * QT_STRIDE + iq0];
            float4 kv = *(float4*)&Kt[d * QT_STRIDE + jk0];
            float qa[4] = {qv.x, qv.y, qv.z, qv.w};
            float ka[4] = {kv.x, kv.y, kv.z, kv.w};
#pragma unroll
            for (int i = 0; i < 4; i++)
#pragma unroll
                for (int j = 0; j < 4; j++)
                    s[i][j] = fmaf(qa[i], ka[j], s[i][j]);
        }
#pragma unroll
        for (int i = 0; i < 4; i++)
#pragma unroll
            for (int j = 0; j < 4; j++)
                Ss[(iq0 + i) * 65 + jk0 + j] = s[i][j] * scale;
        __syncthreads();

        // Online softmax: one thread per row (pad-65 => conflict-free scan)
        if (t < 64) {
            float* row = Ss + t * 65;
            float mo = m_s[t], mn = mo;
#pragma unroll 8
            for (int j = 0; j < 64; j++) mn = fmaxf(mn, row[j]);
            float al = __expf(mo - mn);
            float ls = 0.f;
#pragma unroll 8
            for (int j = 0; j < 64; j++) {
                float p = __expf(row[j] - mn);
                row[j] = p;
                ls += p;
            }
            m_s[t]  = mn;
            l_s[t]  = l_s[t] * al + ls;
            al_s[t] = al;
        }
        __syncthreads();

        // Rescale O, then O += P * V
#pragma unroll
        for (int i = 0; i < 4; i++) {
            float al = al_s[r0 + i];
            o[i][0] *= al; o[i][1] *= al; o[i][2] *= al; o[i][3] *= al;
        }
#pragma unroll 8
        for (int k = 0; k < 64; k++) {
            float4 vv = *(float4*)&Vs[k * 64 + c0];
#pragma unroll
            for (int i = 0; i < 4; i++) {
                float p = Ss[(r0 + i) * 65 + k];
                o[i][0] = fmaf(p, vv.x, o[i][0]);
                o[i][1] = fmaf(p, vv.y, o[i][1]);
                o[i][2] = fmaf(p, vv.z, o[i][2]);
                o[i][3] = fmaf(p, vv.w, o[i][3]);
            }
        }
    }

    // Epilogue: normalize by l and store heads in [B,S,H*Hd] row-major
    float* Obase = O + (b * SEQ + qb) * DMODEL + h * HDIM;
#pragma unroll
    for (int i = 0; i < 4; i++) {
        float inv = 1.f / l_s[r0 + i];
        float4 out;
        out.x = o[i][0] * inv;
        out.y = o[i][1] * inv;
        out.z = o[i][2] * inv;
        out.w = o[i][3] * inv;
        *(float4*)&Obase[(r0 + i) * DMODEL + c0] = out;
    }
}

// ---------------------------------------------------------------------------
extern "C" void kernel_launch(void* const* d_in, const int* in_sizes, int n_in,
                              void* d_out, int out_size)
{
    (void)in_sizes; (void)n_in; (void)out_size;
    const float* x  = (const float*)d_in[0];
    const float* Wq = (const float*)d_in[1];
    const float* bq = (const float*)d_in[2];
    const float* Wk = (const float*)d_in[3];
    const float* bk = (const float*)d_in[4];
    const float* Wv = (const float*)d_in[5];
    const float* bv = (const float*)d_in[6];
    const float* Wo = (const float*)d_in[7];
    const float* bo = (const float*)d_in[8];
    float* out = (float*)d_out;

    float *gq, *gk, *gv, *gh;
    cudaGetSymbolAddress((void**)&gq, g_q);
    cudaGetSymbolAddress((void**)&gk, g_k);
    cudaGetSymbolAddress((void**)&gv, g_v);
    cudaGetSymbolAddress((void**)&gh, g_h);

    dim3 ggrid(DMODEL / 128, MROWS / 128);   // (8, 64)
    sgemm_bias_kernel<<<ggrid, 256>>>(x, Wq, bq, gq);
    sgemm_bias_kernel<<<ggrid, 256>>>(x, Wk, bk, gk);
    sgemm_bias_kernel<<<ggrid, 256>>>(x, Wv, bv, gv);

    cudaFuncSetAttribute(flash_attn_kernel,
                         cudaFuncAttributeMaxDynamicSharedMemorySize,
                         FLASH_SMEM_BYTES);
    flash_attn_kernel<<<dim3(SEQ / 64, BATCH * NHEADS), 256, FLASH_SMEM_BYTES>>>(
        gq, gk, gv, gh);

    sgemm_bias_kernel<<<ggrid, 256>>>(gh, Wo, bo, out);
}

// round 13
// speedup vs baseline: 1.6028x; 1.0007x over previous
#include <cuda_runtime.h>
#include <cuda_bf16.h>

// Problem constants
#define BATCH   4
#define SEQ     2048
#define DMODEL  1024
#define NHEADS  16
#define HDIM    64
#define MROWS   (BATCH * SEQ)          // 8192
#define ELEMS   (MROWS * DMODEL)       // 8388608

// Scratch: Q, K, V, heads  (row-major [M, D]; D index = h*64 + hd)
__device__ float g_q[ELEMS];
__device__ float g_k[ELEMS];
__device__ float g_v[ELEMS];
__device__ float g_h[ELEMS];

// ---------------------------------------------------------------------------
// SGEMM + bias: C[M,1024] = A[M,1024] * B[1024,1024] + bias
// 128x128 block tile, BK=8, 256 threads, 8x8 per-thread microtile.
// ---------------------------------------------------------------------------
__global__ __launch_bounds__(256, 2)
void sgemm_bias_kernel(const float* __restrict__ A, const float* __restrict__ B,
                       const float* __restrict__ bias, float* __restrict__ C)
{
    const int K = 1024, N = 1024;
    __shared__ float As[8 * 128];   // As[k][m]
    __shared__ float Bs[8 * 128];   // Bs[k][n]

    const int t  = threadIdx.x;
    const int bm = blockIdx.y * 128;
    const int bn = blockIdx.x * 128;

    const int arow = t >> 1;          // 0..127
    const int acol = (t & 1) << 2;    // 0 or 4
    const int brow = t >> 5;          // 0..7
    const int bcol = (t & 31) << 2;   // 0..124
    const int ty = t >> 4, tx = t & 15;

    float acc[8][8];
#pragma unroll
    for (int i = 0; i < 8; i++)
#pragma unroll
        for (int j = 0; j < 8; j++) acc[i][j] = 0.f;

    const float* Aptr = A + (bm + arow) * K + acol;
    const float* Bptr = B + brow * N + bn + bcol;

    for (int k0 = 0; k0 < K; k0 += 8) {
        float4 a = *(const float4*)(Aptr + k0);
        float4 b = *(const float4*)(Bptr + k0 * N);
        __syncthreads();
        As[(acol + 0) * 128 + arow] = a.x;
        As[(acol + 1) * 128 + arow] = a.y;
        As[(acol + 2) * 128 + arow] = a.z;
        As[(acol + 3) * 128 + arow] = a.w;
        *(float4*)&Bs[brow * 128 + bcol] = b;
        __syncthreads();
#pragma unroll
        for (int kk = 0; kk < 8; kk++) {
            float4 a0 = *(float4*)&As[kk * 128 + ty * 8];
            float4 a1 = *(float4*)&As[kk * 128 + ty * 8 + 4];
            float4 b0 = *(float4*)&Bs[kk * 128 + tx * 8];
            float4 b1 = *(float4*)&Bs[kk * 128 + tx * 8 + 4];
            float ar[8] = {a0.x, a0.y, a0.z, a0.w, a1.x, a1.y, a1.z, a1.w};
            float br[8] = {b0.x, b0.y, b0.z, b0.w, b1.x, b1.y, b1.z, b1.w};
#pragma unroll
            for (int i = 0; i < 8; i++)
#pragma unroll
                for (int j = 0; j < 8; j++)
                    acc[i][j] = fmaf(ar[i], br[j], acc[i][j]);
        }
    }

#pragma unroll
    for (int i = 0; i < 8; i++) {
        int row = bm + ty * 8 + i;
#pragma unroll
        for (int j0 = 0; j0 < 8; j0 += 4) {
            int col = bn + tx * 8 + j0;
            float4 c;
            c.x = acc[i][j0 + 0] + bias[col + 0];
            c.y = acc[i][j0 + 1] + bias[col + 1];
            c.z = acc[i][j0 + 2] + bias[col + 2];
            c.w = acc[i][j0 + 3] + bias[col + 3];
            *(float4*)&C[row * N + col] = c;
        }
    }
}

// ---------------------------------------------------------------------------
// Flash attention: one block handles (b,h) and 64 query rows.
// Br = Bc = 64, Hd = 64. Online softmax, O accumulated in registers.
// Smem (dynamic, 68608 B):
//   Qt[64 d][68] transposed Q tile (stride 68: 16B-aligned + bank rotation)
//   Kt[64 d][68] transposed K tile
//   Vs[64 k][64 c]
//   Ss[64 r][65]  scores/probs (pad 65 -> conflict-free row scans)
//   m_s/l_s/al_s[64] row stats
// ---------------------------------------------------------------------------
#define QT_STRIDE 68
#define FLASH_SMEM_FLOATS (64*QT_STRIDE*2 + 64*64 + 64*65 + 3*64)
#define FLASH_SMEM_BYTES  (FLASH_SMEM_FLOATS * 4)

__global__ __launch_bounds__(256, 2)
void flash_attn_kernel(const float* __restrict__ Q, const float* __restrict__ Kg,
                       const float* __restrict__ Vg, float* __restrict__ O)
{
    extern __shared__ float sm[];
    float* Qt   = sm;                        // 64*68
    float* Kt   = Qt + 64 * QT_STRIDE;       // 64*68
    float* Vs   = Kt + 64 * QT_STRIDE;       // 64*64
    float* Ss   = Vs + 64 * 64;              // 64*65
    float* m_s  = Ss + 64 * 65;
    float* l_s  = m_s + 64;
    float* al_s = l_s + 64;

    const int t  = threadIdx.x;
    const int qb = blockIdx.x * 64;
    const int bh = blockIdx.y;               // b*16 + h
    const int b  = bh >> 4;
    const int h  = bh & 15;
    const float scale = 0.125f;              // 1/sqrt(64)

    const int tx = t & 15, ty = t >> 4;
    const int iq0 = tx * 4, jk0 = ty * 4;    // QK^T microtile
    const int r0  = ty * 4, c0  = tx * 4;    // PV / O microtile

    // Load Q tile transposed: Qt[d][i]
    const float* Qbase = Q + (b * SEQ + qb) * DMODEL + h * HDIM;
    for (int e = t * 4; e < 64 * 64; e += 1024) {
        int i = e >> 6, d = e & 63;
        float4 v = *(const float4*)&Qbase[i * DMODEL + d];
        Qt[(d + 0) * QT_STRIDE + i] = v.x;
        Qt[(d + 1) * QT_STRIDE + i] = v.y;
        Qt[(d + 2) * QT_STRIDE + i] = v.z;
        Qt[(d + 3) * QT_STRIDE + i] = v.w;
    }
    if (t < 64) { m_s[t] = -1e30f; l_s[t] = 0.f; }

    float o[4][4];
#pragma unroll
    for (int i = 0; i < 4; i++)
#pragma unroll
        for (int j = 0; j < 4; j++) o[i][j] = 0.f;

    for (int kb = 0; kb < SEQ; kb += 64) {
        __syncthreads();   // previous tile's Ss/Vs reads complete

        // Load K (transposed) and V tiles
        const float* Kbase = Kg + (b * SEQ + kb) * DMODEL + h * HDIM;
        const float* Vbase = Vg + (b * SEQ + kb) * DMODEL + h * HDIM;
        for (int e = t * 4; e < 64 * 64; e += 1024) {
            int j = e >> 6, d = e & 63;
            float4 v = *(const float4*)&Kbase[j * DMODEL + d];
            Kt[(d + 0) * QT_STRIDE + j] = v.x;
            Kt[(d + 1) * QT_STRIDE + j] = v.y;
            Kt[(d + 2) * QT_STRIDE + j] = v.z;
            Kt[(d + 3) * QT_STRIDE + j] = v.w;
            float4 w = *(const float4*)&Vbase[j * DMODEL + d];
            *(float4*)&Vs[j * 64 + d] = w;
        }
        __syncthreads();

        // S = Q * K^T (scaled), microtile 4x4 per thread
        float s[4][4];
#pragma unroll
        for (int i = 0; i < 4; i++)
#pragma unroll
            for (int j = 0; j < 4; j++) s[i][j] = 0.f;
#pragma unroll 8
        for (int d = 0; d < 64; d++) {
            float4 qv = *(float4*)&Qt[d * QT_STRIDE + iq0];
            float4 kv = *(float4*)&Kt[d * QT_STRIDE + jk0];
            float qa[4] = {qv.x, qv.y, qv.z, qv.w};
            float ka[4] = {kv.x, kv.y, kv.z, kv.w};
#pragma unroll
            for (int i = 0; i < 4; i++)
#pragma unroll
                for (int j = 0; j < 4; j++)
                    s[i][j] = fmaf(qa[i], ka[j], s[i][j]);
        }
#pragma unroll
        for (int i = 0; i < 4; i++)
#pragma unroll
            for (int j = 0; j < 4; j++)
                Ss[(iq0 + i) * 65 + jk0 + j] = s[i][j] * scale;
        __syncthreads();

        // Online softmax: one thread per row (pad-65 => conflict-free scan)
        if (t < 64) {
            float* row = Ss + t * 65;
            float mo = m_s[t], mn = mo;
#pragma unroll 8
            for (int j = 0; j < 64; j++) mn = fmaxf(mn, row[j]);
            float al = __expf(mo - mn);
            float ls = 0.f;
#pragma unroll 8
            for (int j = 0; j < 64; j++) {
                float p = __expf(row[j] - mn);
                row[j] = p;
                ls += p;
            }
            m_s[t]  = mn;
            l_s[t]  = l_s[t] * al + ls;
            al_s[t] = al;
        }
        __syncthreads();

        // Rescale O, then O += P * V
#pragma unroll
        for (int i = 0; i < 4; i++) {
            float al = al_s[r0 + i];
            o[i][0] *= al; o[i][1] *= al; o[i][2] *= al; o[i][3] *= al;
        }
#pragma unroll 8
        for (int k = 0; k < 64; k++) {
            float4 vv = *(float4*)&Vs[k * 64 + c0];
#pragma unroll
            for (int i = 0; i < 4; i++) {
                float p = Ss[(r0 + i) * 65 + k];
                o[i][0] = fmaf(p, vv.x, o[i][0]);
                o[i][1] = fmaf(p, vv.y, o[i][1]);
                o[i][2] = fmaf(p, vv.z, o[i][2]);
                o[i][3] = fmaf(p, vv.w, o[i][3]);
            }
        }
    }

    // Epilogue: normalize by l and store heads in [B,S,H*Hd] row-major
    float* Obase = O + (b * SEQ + qb) * DMODEL + h * HDIM;
#pragma unroll
    for (int i = 0; i < 4; i++) {
        float inv = 1.f / l_s[r0 + i];
        float4 out;
        out.x = o[i][0] * inv;
        out.y = o[i][1] * inv;
        out.z = o[i][2] * inv;
        out.w = o[i][3] * inv;
        *(float4*)&Obase[(r0 + i) * DMODEL + c0] = out;
    }
}

// ---------------------------------------------------------------------------
extern "C" void kernel_launch(void* const* d_in, const int* in_sizes, int n_in,
                              void* d_out, int out_size)
{
    (void)in_sizes; (void)n_in; (void)out_size;
    const float* x  = (const float*)d_in[0];
    const float* Wq = (const float*)d_in[1];
    const float* bq = (const float*)d_in[2];
    const float* Wk = (const float*)d_in[3];
    const float* bk = (const float*)d_in[4];
    const float* Wv = (const float*)d_in[5];
    const float* bv = (const float*)d_in[6];
    const float* Wo = (const float*)d_in[7];
    const float* bo = (const float*)d_in[8];
    float* out = (float*)d_out;

    float *gq, *gk, *gv, *gh;
    cudaGetSymbolAddress((void**)&gq, g_q);
    cudaGetSymbolAddress((void**)&gk, g_k);
    cudaGetSymbolAddress((void**)&gv, g_v);
    cudaGetSymbolAddress((void**)&gh, g_h);

    dim3 ggrid(DMODEL / 128, MROWS / 128);   // (8, 64)
    sgemm_bias_kernel<<<ggrid, 256>>>(x, Wq, bq, gq);
    sgemm_bias_kernel<<<ggrid, 256>>>(x, Wk, bk, gk);
    sgemm_bias_kernel<<<ggrid, 256>>>(x, Wv, bv, gv);

    cudaFuncSetAttribute(flash_attn_kernel,
                         cudaFuncAttributeMaxDynamicSharedMemorySize,
                         FLASH_SMEM_BYTES);
    flash_attn_kernel<<<dim3(SEQ / 64, BATCH * NHEADS), 256, FLASH_SMEM_BYTES>>>(
        gq, gk, gv, gh);

    sgemm_bias_kernel<<<ggrid, 256>>>(gh, Wo, bo, out);
}

// round 14
// speedup vs baseline: 1.6039x; 1.0007x over previous
#include <cuda_runtime.h>
#include <cuda_bf16.h>

// Problem constants
#define BATCH   4
#define SEQ     2048
#define DMODEL  1024
#define NHEADS  16
#define HDIM    64
#define MROWS   (BATCH * SEQ)          // 8192
#define ELEMS   (MROWS * DMODEL)       // 8388608

// Scratch: Q, K, V, heads  (row-major [M, D]; D index = h*64 + hd)
__device__ float g_q[ELEMS];
__device__ float g_k[ELEMS];
__device__ float g_v[ELEMS];
__device__ float g_h[ELEMS];

// ---------------------------------------------------------------------------
// SGEMM + bias: C[M,1024] = A[M,1024] * B[1024,1024] + bias
// 128x128 block tile, BK=8, 256 threads, 8x8 per-thread microtile.
// ---------------------------------------------------------------------------
__global__ __launch_bounds__(256, 2)
void sgemm_bias_kernel(const float* __restrict__ A, const float* __restrict__ B,
                       const float* __restrict__ bias, float* __restrict__ C)
{
    const int K = 1024, N = 1024;
    __shared__ float As[8 * 128];   // As[k][m]
    __shared__ float Bs[8 * 128];   // Bs[k][n]

    const int t  = threadIdx.x;
    const int bm = blockIdx.y * 128;
    const int bn = blockIdx.x * 128;

    const int arow = t >> 1;          // 0..127
    const int acol = (t & 1) << 2;    // 0 or 4
    const int brow = t >> 5;          // 0..7
    const int bcol = (t & 31) << 2;   // 0..124
    const int ty = t >> 4, tx = t & 15;

    float acc[8][8];
#pragma unroll
    for (int i = 0; i < 8; i++)
#pragma unroll
        for (int j = 0; j < 8; j++) acc[i][j] = 0.f;

    const float* Aptr = A + (bm + arow) * K + acol;
    const float* Bptr = B + brow * N + bn + bcol;

    for (int k0 = 0; k0 < K; k0 += 8) {
        float4 a = *(const float4*)(Aptr + k0);
        float4 b = *(const float4*)(Bptr + k0 * N);
        __syncthreads();
        As[(acol + 0) * 128 + arow] = a.x;
        As[(acol + 1) * 128 + arow] = a.y;
        As[(acol + 2) * 128 + arow] = a.z;
        As[(acol + 3) * 128 + arow] = a.w;
        *(float4*)&Bs[brow * 128 + bcol] = b;
        __syncthreads();
#pragma unroll
        for (int kk = 0; kk < 8; kk++) {
            float4 a0 = *(float4*)&As[kk * 128 + ty * 8];
            float4 a1 = *(float4*)&As[kk * 128 + ty * 8 + 4];
            float4 b0 = *(float4*)&Bs[kk * 128 + tx * 8];
            float4 b1 = *(float4*)&Bs[kk * 128 + tx * 8 + 4];
            float ar[8] = {a0.x, a0.y, a0.z, a0.w, a1.x, a1.y, a1.z, a1.w};
            float br[8] = {b0.x, b0.y, b0.z, b0.w, b1.x, b1.y, b1.z, b1.w};
#pragma unroll
            for (int i = 0; i < 8; i++)
#pragma unroll
                for (int j = 0; j < 8; j++)
                    acc[i][j] = fmaf(ar[i], br[j], acc[i][j]);
        }
    }

#pragma unroll
    for (int i = 0; i < 8; i++) {
        int row = bm + ty * 8 + i;
#pragma unroll
        for (int j0 = 0; j0 < 8; j0 += 4) {
            int col = bn + tx * 8 + j0;
            float4 c;
            c.x = acc[i][j0 + 0] + bias[col + 0];
            c.y = acc[i][j0 + 1] + bias[col + 1];
            c.z = acc[i][j0 + 2] + bias[col + 2];
            c.w = acc[i][j0 + 3] + bias[col + 3];
            *(float4*)&C[row * N + col] = c;
        }
    }
}

// ---------------------------------------------------------------------------
// Flash attention: one block handles (b,h) and 64 query rows.
// Br = Bc = 64, Hd = 64. Online softmax, O accumulated in registers.
// Smem (dynamic, 68608 B):
//   Qt[64 d][68] transposed Q tile (stride 68: 16B-aligned + bank rotation)
//   Kt[64 d][68] transposed K tile
//   Vs[64 k][64 c]
//   Ss[64 r][65]  scores/probs (pad 65 -> conflict-free row scans)
//   m_s/l_s/al_s[64] row stats
// ---------------------------------------------------------------------------
#define QT_STRIDE 68
#define FLASH_SMEM_FLOATS (64*QT_STRIDE*2 + 64*64 + 64*65 + 3*64)
#define FLASH_SMEM_BYTES  (FLASH_SMEM_FLOATS * 4)

__global__ __launch_bounds__(256, 2)
void flash_attn_kernel(const float* __restrict__ Q, const float* __restrict__ Kg,
                       const float* __restrict__ Vg, float* __restrict__ O)
{
    extern __shared__ float sm[];
    float* Qt   = sm;                        // 64*68
    float* Kt   = Qt + 64 * QT_STRIDE;       // 64*68
    float* Vs   = Kt + 64 * QT_STRIDE;       // 64*64
    float* Ss   = Vs + 64 * 64;              // 64*65
    float* m_s  = Ss + 64 * 65;
    float* l_s  = m_s + 64;
    float* al_s = l_s + 64;

    const int t  = threadIdx.x;
    const int qb = blockIdx.x * 64;
    const int bh = blockIdx.y;               // b*16 + h
    const int b  = bh >> 4;
    const int h  = bh & 15;
    const float scale = 0.125f;              // 1/sqrt(64)

    const int tx = t & 15, ty = t >> 4;
    const int iq0 = tx * 4, jk0 = ty * 4;    // QK^T microtile
    const int r0  = ty * 4, c0  = tx * 4;    // PV / O microtile

    // Load Q tile transposed: Qt[d][i]
    const float* Qbase = Q + (b * SEQ + qb) * DMODEL + h * HDIM;
    for (int e = t * 4; e < 64 * 64; e += 1024) {
        int i = e >> 6, d = e & 63;
        float4 v = *(const float4*)&Qbase[i * DMODEL + d];
        Qt[(d + 0) * QT_STRIDE + i] = v.x;
        Qt[(d + 1) * QT_STRIDE + i] = v.y;
        Qt[(d + 2) * QT_STRIDE + i] = v.z;
        Qt[(d + 3) * QT_STRIDE + i] = v.w;
    }
    if (t < 64) { m_s[t] = -1e30f; l_s[t] = 0.f; }

    float o[4][4];
#pragma unroll
    for (int i = 0; i < 4; i++)
#pragma unroll
        for (int j = 0; j < 4; j++) o[i][j] = 0.f;

    for (int kb = 0; kb < SEQ; kb += 64) {
        __syncthreads();   // previous tile's Ss/Vs reads complete

        // Load K (transposed) and V tiles
        const float* Kbase = Kg + (b * SEQ + kb) * DMODEL + h * HDIM;
        const float* Vbase = Vg + (b * SEQ + kb) * DMODEL + h * HDIM;
        for (int e = t * 4; e < 64 * 64; e += 1024) {
            int j = e >> 6, d = e & 63;
            float4 v = *(const float4*)&Kbase[j * DMODEL + d];
            Kt[(d + 0) * QT_STRIDE + j] = v.x;
            Kt[(d + 1) * QT_STRIDE + j] = v.y;
            Kt[(d + 2) * QT_STRIDE + j] = v.z;
            Kt[(d + 3) * QT_STRIDE + j] = v.w;
            float4 w = *(const float4*)&Vbase[j * DMODEL + d];
            *(float4*)&Vs[j * 64 + d] = w;
        }
        __syncthreads();

        // S = Q * K^T (scaled), microtile 4x4 per thread
        float s[4][4];
#pragma unroll
        for (int i = 0; i < 4; i++)
#pragma unroll
            for (int j = 0; j < 4; j++) s[i][j] = 0.f;
#pragma unroll 8
        for (int d = 0; d < 64; d++) {
            float4 qv = *(float4*)&Qt[d * QT_STRIDE + iq0];
            float4 kv = *(float4*)&Kt[d * QT_STRIDE + jk0];
            float qa[4] = {qv.x, qv.y, qv.z, qv.w};
            float ka[4] = {kv.x, kv.y, kv.z, kv.w};
#pragma unroll
            for (int i = 0; i < 4; i++)
#pragma unroll
                for (int j = 0; j < 4; j++)
                    s[i][j] = fmaf(qa[i], ka[j], s[i][j]);
        }
#pragma unroll
        for (int i = 0; i < 4; i++)
#pragma unroll
            for (int j = 0; j < 4; j++)
                Ss[(iq0 + i) * 65 + jk0 + j] = s[i][j] * scale;
        __syncthreads();

        // Online softmax: one thread per row (pad-65 => conflict-free scan)
        if (t < 64) {
            float* row = Ss + t * 65;
            float mo = m_s[t], mn = mo;
#pragma unroll 8
            for (int j = 0; j < 64; j++) mn = fmaxf(mn, row[j]);
            float al = __expf(mo - mn);
            float ls = 0.f;
#pragma unroll 8
            for (int j = 0; j < 64; j++) {
                float p = __expf(row[j] - mn);
                row[j] = p;
                ls += p;
            }
            m_s[t]  = mn;
            l_s[t]  = l_s[t] * al + ls;
            al_s[t] = al;
        }
        __syncthreads();

        // Rescale O, then O += P * V
#pragma unroll
        for (int i = 0; i < 4; i++) {
            float al = al_s[r0 + i];
            o[i][0] *= al; o[i][1] *= al; o[i][2] *= al; o[i][3] *= al;
        }
#pragma unroll 8
        for (int k = 0; k < 64; k++) {
            float4 vv = *(float4*)&Vs[k * 64 + c0];
#pragma unroll
            for (int i = 0; i < 4; i++) {
                float p = Ss[(r0 + i) * 65 + k];
                o[i][0] = fmaf(p, vv.x, o[i][0]);
                o[i][1] = fmaf(p, vv.y, o[i][1]);
                o[i][2] = fmaf(p, vv.z, o[i][2]);
                o[i][3] = fmaf(p, vv.w, o[i][3]);
            }
        }
    }

    // Epilogue: normalize by l and store heads in [B,S,H*Hd] row-major
    float* Obase = O + (b * SEQ + qb) * DMODEL + h * HDIM;
#pragma unroll
    for (int i = 0; i < 4; i++) {
        float inv = 1.f / l_s[r0 + i];
        float4 out;
        out.x = o[i][0] * inv;
        out.y = o[i][1] * inv;
        out.z = o[i][2] * inv;
        out.w = o[i][3] * inv;
        *(float4*)&Obase[(r0 + i) * DMODEL + c0] = out;
    }
}

// ---------------------------------------------------------------------------
extern "C" void kernel_launch(void* const* d_in, const int* in_sizes, int n_in,
                              void* d_out, int out_size)
{
    (void)in_sizes; (void)n_in; (void)out_size;
    const float* x  = (const float*)d_in[0];
    const float* Wq = (const float*)d_in[1];
    const float* bq = (const float*)d_in[2];
    const float* Wk = (const float*)d_in[3];
    const float* bk = (const float*)d_in[4];
    const float* Wv = (const float*)d_in[5];
    const float* bv = (const float*)d_in[6];
    const float* Wo = (const float*)d_in[7];
    const float* bo = (const float*)d_in[8];
    float* out = (float*)d_out;

    float *gq, *gk, *gv, *gh;
    cudaGetSymbolAddress((void**)&gq, g_q);
    cudaGetSymbolAddress((void**)&gk, g_k);
    cudaGetSymbolAddress((void**)&gv, g_v);
    cudaGetSymbolAddress((void**)&gh, g_h);

    dim3 ggrid(DMODEL / 128, MROWS / 128);   // (8, 64)
    sgemm_bias_kernel<<<ggrid, 256>>>(x, Wq, bq, gq);
    sgemm_bias_kernel<<<ggrid, 256>>>(x, Wk, bk, gk);
    sgemm_bias_kernel<<<ggrid, 256>>>(x, Wv, bv, gv);

    cudaFuncSetAttribute(flash_attn_kernel,
                         cudaFuncAttributeMaxDynamicSharedMemorySize,
                         FLASH_SMEM_BYTES);
    flash_attn_kernel<<<dim3(SEQ / 64, BATCH * NHEADS), 256, FLASH_SMEM_BYTES>>>(
        gq, gk, gv, gh);

    sgemm_bias_kernel<<<ggrid, 256>>>(gh, Wo, bo, out);
}

// round 15
// speedup vs baseline: 4.3377x; 2.7044x over previous
#include <cuda_runtime.h>
#include <cuda_bf16.h>

#define BATCH   4
#define SEQ     2048
#define DMODEL  1024
#define NHEADS  16
#define HDIM    64
#define MROWS   (BATCH * SEQ)
#define ELEMS   (MROWS * DMODEL)

// Scratch: Q, K, V, heads (row-major [M, D]; D index = h*64 + hd)
__device__ float g_q[ELEMS];
__device__ float g_k[ELEMS];
__device__ float g_v[ELEMS];
__device__ float g_h[ELEMS];

// ---------------------------------------------------------------------------
// tf32 helpers
// ---------------------------------------------------------------------------
__device__ __forceinline__ unsigned f2tf(float x) {
    unsigned u;
    asm("cvt.rna.tf32.f32 %0, %1;" : "=r"(u) : "f"(x));
    return u;
}

// D += A(16x8,row) * B(8x8,col); tf32 inputs, f32 accumulate.
__device__ __forceinline__ void mma8(float d[4], const unsigned a[4], const unsigned b[2]) {
    asm volatile(
        "mma.sync.aligned.m16n8k8.row.col.f32.tf32.tf32.f32 "
        "{%0,%1,%2,%3}, {%4,%5,%6,%7}, {%8,%9}, {%0,%1,%2,%3};\n"
        : "+f"(d[0]), "+f"(d[1]), "+f"(d[2]), "+f"(d[3])
        : "r"(a[0]), "r"(a[1]), "r"(a[2]), "r"(a[3]),
          "r"(b[0]), "r"(b[1]));
}

// ---------------------------------------------------------------------------
// tf32 GEMM + bias: C[M,1024] = A[M,1024] * B[1024,1024] + bias
// 128x128 block, BK=16, 256 threads (8 warps, 2x4), warp tile 64x32.
// As[m][k] stride 20 (bank = 20g+t4, all distinct mod 32)
// Bs[k][n] stride 136 (bank = 8t4+g, all distinct mod 32)
// ---------------------------------------------------------------------------
#define AST 20
#define BST 136

__global__ __launch_bounds__(256, 2)
void sgemm_tf32_kernel(const float* __restrict__ A, const float* __restrict__ B,
                       const float* __restrict__ bias, float* __restrict__ C)
{
    const int K = 1024, N = 1024;
    __shared__ unsigned As[128 * AST];
    __shared__ unsigned Bs[16 * BST];

    const int t  = threadIdx.x;
    const int bm = blockIdx.y * 128, bn = blockIdx.x * 128;
    const int l  = t & 31, g = l >> 2, t4 = l & 3;
    const int w  = t >> 5, wm = w >> 2, wn = w & 3;   // 2 x 4 warp grid

    const int arow = t >> 1,  acol = (t & 1) * 8;     // A: 128 rows x 16 cols
    const int brow = t >> 4,  bcol = (t & 15) * 8;    // B: 16 rows x 128 cols

    float acc[4][4][4];
#pragma unroll
    for (int mi = 0; mi < 4; mi++)
#pragma unroll
        for (int ni = 0; ni < 4; ni++)
#pragma unroll
            for (int r = 0; r < 4; r++) acc[mi][ni][r] = 0.f;

    const float* Ap = A + (size_t)(bm + arow) * K + acol;
    const float* Bp = B + (size_t)brow * N + bn + bcol;

    for (int k0 = 0; k0 < K; k0 += 16) {
        float4 av0 = *(const float4*)(Ap + k0);
        float4 av1 = *(const float4*)(Ap + k0 + 4);
        float4 bv0 = *(const float4*)(Bp + (size_t)k0 * N);
        float4 bv1 = *(const float4*)(Bp + (size_t)k0 * N + 4);
        __syncthreads();
        *(uint4*)&As[arow * AST + acol]     = make_uint4(f2tf(av0.x), f2tf(av0.y), f2tf(av0.z), f2tf(av0.w));
        *(uint4*)&As[arow * AST + acol + 4] = make_uint4(f2tf(av1.x), f2tf(av1.y), f2tf(av1.z), f2tf(av1.w));
        *(uint4*)&Bs[brow * BST + bcol]     = make_uint4(f2tf(bv0.x), f2tf(bv0.y), f2tf(bv0.z), f2tf(bv0.w));
        *(uint4*)&Bs[brow * BST + bcol + 4] = make_uint4(f2tf(bv1.x), f2tf(bv1.y), f2tf(bv1.z), f2tf(bv1.w));
        __syncthreads();

#pragma unroll
        for (int kc = 0; kc < 16; kc += 8) {
            unsigned a[4][4], b[4][2];
#pragma unroll
            for (int mi = 0; mi < 4; mi++) {
                int rm = wm * 64 + mi * 16;
                a[mi][0] = As[(rm + g)     * AST + kc + t4];
                a[mi][1] = As[(rm + g + 8) * AST + kc + t4];
                a[mi][2] = As[(rm + g)     * AST + kc + t4 + 4];
                a[mi][3] = As[(rm + g + 8) * AST + kc + t4 + 4];
            }
#pragma unroll
            for (int ni = 0; ni < 4; ni++) {
                int cn = wn * 32 + ni * 8;
                b[ni][0] = Bs[(kc + t4)     * BST + cn + g];
                b[ni][1] = Bs[(kc + t4 + 4) * BST + cn + g];
            }
#pragma unroll
            for (int mi = 0; mi < 4; mi++)
#pragma unroll
                for (int ni = 0; ni < 4; ni++)
                    mma8(acc[mi][ni], a[mi], b[ni]);
        }
    }

#pragma unroll
    for (int mi = 0; mi < 4; mi++) {
        int r0 = bm + wm * 64 + mi * 16 + g;
#pragma unroll
        for (int ni = 0; ni < 4; ni++) {
            int c = bn + wn * 32 + ni * 8 + 2 * t4;
            float b0 = bias[c], b1 = bias[c + 1];
            *(float2*)&C[(size_t)r0 * N + c] =
                make_float2(acc[mi][ni][0] + b0, acc[mi][ni][1] + b1);
            *(float2*)&C[(size_t)(r0 + 8) * N + c] =
                make_float2(acc[mi][ni][2] + b0, acc[mi][ni][3] + b1);
        }
    }
}

// ---------------------------------------------------------------------------
// Flash attention, tf32 mma. Block = (b,h) x 64 query rows. Br=Bc=64, Hd=64.
// 256 threads, 8 warps (4 m-tiles x 2 n-tiles), warp tile 16x32.
// Layouts (all native row-major, conflict-free fragment reads):
//   Qs[i][d] stride 68, Ks[j][d] stride 68 (bank 4g+t4, distinct)
//   Vs[j][d] stride 72 (bank 8t4+g, distinct)
//   Ss[q][k] stride 68 (mma reads + 4-lane/row softmax both conflict-free)
// ---------------------------------------------------------------------------
#define QST 68
#define KST 68
#define VST 72
#define SST 68
#define FL_K (64 * QST)
#define FL_V (FL_K + 64 * KST)
#define FL_S (FL_V + 64 * VST)
#define FL_M (FL_S + 64 * SST)
#define FL_FLOATS (FL_M + 3 * 64)
#define FL_BYTES  (FL_FLOATS * 4)

__global__ __launch_bounds__(256, 2)
void flash_tf32_kernel(const float* __restrict__ Q, const float* __restrict__ Kg,
                       const float* __restrict__ Vg, float* __restrict__ O)
{
    extern __shared__ unsigned sm[];
    unsigned* Qs = sm;
    unsigned* Ks = sm + FL_K;
    unsigned* Vs = sm + FL_V;
    unsigned* Ss = sm + FL_S;
    float* m_s  = (float*)(sm + FL_M);
    float* l_s  = m_s + 64;
    float* al_s = l_s + 64;

    const int t  = threadIdx.x;
    const int l  = t & 31, g = l >> 2, t4 = l & 3;
    const int w  = t >> 5, wm = w & 3, wn = w >> 1 >> 1 >> 0;  // wn = w>>2
    const int wn2 = w >> 2;
    const int q0 = wm * 16, c0 = wn2 * 32;
    (void)wn;

    const int qb = blockIdx.x * 64;
    const int bh = blockIdx.y, b = bh >> 4, h = bh & 15;
    const float scale = 0.125f;   // 1/sqrt(64)

    // Load Q tile (native layout, cvt to tf32)
    const float* Qb = Q + (size_t)(b * SEQ + qb) * DMODEL + h * HDIM;
#pragma unroll
    for (int e = t * 4; e < 64 * 64; e += 1024) {
        int i = e >> 6, d = e & 63;
        float4 v = *(const float4*)&Qb[i * DMODEL + d];
        *(uint4*)&Qs[i * QST + d] = make_uint4(f2tf(v.x), f2tf(v.y), f2tf(v.z), f2tf(v.w));
    }
    if (t < 64) { m_s[t] = -1e30f; l_s[t] = 0.f; }

    float o[4][4];
#pragma unroll
    for (int ni = 0; ni < 4; ni++)
#pragma unroll
        for (int r = 0; r < 4; r++) o[ni][r] = 0.f;

    for (int kb = 0; kb < SEQ; kb += 64) {
        __syncthreads();
        const float* Kb = Kg + (size_t)(b * SEQ + kb) * DMODEL + h * HDIM;
        const float* Vb = Vg + (size_t)(b * SEQ + kb) * DMODEL + h * HDIM;
#pragma unroll
        for (int e = t * 4; e < 64 * 64; e += 1024) {
            int j = e >> 6, d = e & 63;
            float4 v = *(const float4*)&Kb[j * DMODEL + d];
            *(uint4*)&Ks[j * KST + d] = make_uint4(f2tf(v.x), f2tf(v.y), f2tf(v.z), f2tf(v.w));
            float4 u = *(const float4*)&Vb[j * DMODEL + d];
            *(uint4*)&Vs[j * VST + d] = make_uint4(f2tf(u.x), f2tf(u.y), f2tf(u.z), f2tf(u.w));
        }
        __syncthreads();

        // S = Q * K^T
        float s[4][4];
#pragma unroll
        for (int ni = 0; ni < 4; ni++)
#pragma unroll
            for (int r = 0; r < 4; r++) s[ni][r] = 0.f;
#pragma unroll
        for (int kc = 0; kc < 64; kc += 8) {
            unsigned a[4];
            a[0] = Qs[(q0 + g)     * QST + kc + t4];
            a[1] = Qs[(q0 + g + 8) * QST + kc + t4];
            a[2] = Qs[(q0 + g)     * QST + kc + t4 + 4];
            a[3] = Qs[(q0 + g + 8) * QST + kc + t4 + 4];
#pragma unroll
            for (int ni = 0; ni < 4; ni++) {
                unsigned bb[2];
                bb[0] = Ks[(c0 + ni * 8 + g) * KST + kc + t4];
                bb[1] = Ks[(c0 + ni * 8 + g) * KST + kc + t4 + 4];
                mma8(s[ni], a, bb);
            }
        }
        // Store scaled scores (fp32 bits)
#pragma unroll
        for (int ni = 0; ni < 4; ni++) {
            int c = c0 + ni * 8 + 2 * t4;
            *(uint2*)&Ss[(q0 + g) * SST + c] =
                make_uint2(__float_as_uint(s[ni][0] * scale), __float_as_uint(s[ni][1] * scale));
            *(uint2*)&Ss[(q0 + g + 8) * SST + c] =
                make_uint2(__float_as_uint(s[ni][2] * scale), __float_as_uint(s[ni][3] * scale));
        }
        __syncthreads();

        // Online softmax: 4 lanes per row (row = t>>2), conflict-free strided scan.
        {
            int r = t >> 2;
            unsigned* row = Ss + r * SST;
            float mo = m_s[r];
            float pv[16];
            float mn = mo;
#pragma unroll
            for (int jj = 0; jj < 16; jj++) {
                float x = __uint_as_float(row[t4 + jj * 4]);
                pv[jj] = x;
                mn = fmaxf(mn, x);
            }
            mn = fmaxf(mn, __shfl_xor_sync(0xffffffffu, mn, 1));
            mn = fmaxf(mn, __shfl_xor_sync(0xffffffffu, mn, 2));
            float ls = 0.f;
#pragma unroll
            for (int jj = 0; jj < 16; jj++) {
                float p = __expf(pv[jj] - mn);
                ls += p;
                row[t4 + jj * 4] = f2tf(p);   // write P as tf32 for PV mma
            }
            ls += __shfl_xor_sync(0xffffffffu, ls, 1);
            ls += __shfl_xor_sync(0xffffffffu, ls, 2);
            if (t4 == 0) {
                float al = __expf(mo - mn);
                m_s[r]  = mn;
                l_s[r]  = l_s[r] * al + ls;
                al_s[r] = al;
            }
        }
        __syncthreads();

        // Rescale O, then O += P * V
        float al0 = al_s[q0 + g], al1 = al_s[q0 + g + 8];
#pragma unroll
        for (int ni = 0; ni < 4; ni++) {
            o[ni][0] *= al0; o[ni][1] *= al0;
            o[ni][2] *= al1; o[ni][3] *= al1;
        }
#pragma unroll
        for (int kc = 0; kc < 64; kc += 8) {
            unsigned a[4];
            a[0] = Ss[(q0 + g)     * SST + kc + t4];
            a[1] = Ss[(q0 + g + 8) * SST + kc + t4];
            a[2] = Ss[(q0 + g)     * SST + kc + t4 + 4];
            a[3] = Ss[(q0 + g + 8) * SST + kc + t4 + 4];
#pragma unroll
            for (int ni = 0; ni < 4; ni++) {
                unsigned bb[2];
                bb[0] = Vs[(kc + t4)     * VST + c0 + ni * 8 + g];
                bb[1] = Vs[(kc + t4 + 4) * VST + c0 + ni * 8 + g];
                mma8(o[ni], a, bb);
            }
        }
    }

    // Epilogue: normalize and store heads
    float inv0 = 1.f / l_s[q0 + g], inv1 = 1.f / l_s[q0 + g + 8];
    float* Ob = O + (size_t)(b * SEQ + qb) * DMODEL + h * HDIM;
#pragma unroll
    for (int ni = 0; ni < 4; ni++) {
        int c = c0 + ni * 8 + 2 * t4;
        *(float2*)&Ob[(q0 + g) * DMODEL + c]     = make_float2(o[ni][0] * inv0, o[ni][1] * inv0);
        *(float2*)&Ob[(q0 + g + 8) * DMODEL + c] = make_float2(o[ni][2] * inv1, o[ni][3] * inv1);
    }
}

// ---------------------------------------------------------------------------
extern "C" void kernel_launch(void* const* d_in, const int* in_sizes, int n_in,
                              void* d_out, int out_size)
{
    (void)in_sizes; (void)n_in; (void)out_size;
    const float* x  = (const float*)d_in[0];
    const float* Wq = (const float*)d_in[1];
    const float* bq = (const float*)d_in[2];
    const float* Wk = (const float*)d_in[3];
    const float* bk = (const float*)d_in[4];
    const float* Wv = (const float*)d_in[5];
    const float* bv = (const float*)d_in[6];
    const float* Wo = (const float*)d_in[7];
    const float* bo = (const float*)d_in[8];
    float* out = (float*)d_out;

    float *gq, *gk, *gv, *gh;
    cudaGetSymbolAddress((void**)&gq, g_q);
    cudaGetSymbolAddress((void**)&gk, g_k);
    cudaGetSymbolAddress((void**)&gv, g_v);
    cudaGetSymbolAddress((void**)&gh, g_h);

    dim3 ggrid(DMODEL / 128, MROWS / 128);   // (8, 64)
    sgemm_tf32_kernel<<<ggrid, 256>>>(x, Wq, bq, gq);
    sgemm_tf32_kernel<<<ggrid, 256>>>(x, Wk, bk, gk);
    sgemm_tf32_kernel<<<ggrid, 256>>>(x, Wv, bv, gv);

    cudaFuncSetAttribute(flash_tf32_kernel,
                         cudaFuncAttributeMaxDynamicSharedMemorySize,
                         FL_BYTES);
    flash_tf32_kernel<<<dim3(SEQ / 64, BATCH * NHEADS), 256, FL_BYTES>>>(
        gq, gk, gv, gh);

    sgemm_tf32_kernel<<<ggrid, 256>>>(gh, Wo, bo, out);
}

// round 16
// speedup vs baseline: 4.3381x; 1.0001x over previous
#include <cuda_runtime.h>
#include <cuda_bf16.h>

#define BATCH   4
#define SEQ     2048
#define DMODEL  1024
#define NHEADS  16
#define HDIM    64
#define MROWS   (BATCH * SEQ)
#define ELEMS   (MROWS * DMODEL)

// Scratch: Q, K, V, heads (row-major [M, D]; D index = h*64 + hd)
__device__ float g_q[ELEMS];
__device__ float g_k[ELEMS];
__device__ float g_v[ELEMS];
__device__ float g_h[ELEMS];

// ---------------------------------------------------------------------------
// tf32 helpers
// ---------------------------------------------------------------------------
__device__ __forceinline__ unsigned f2tf(float x) {
    unsigned u;
    asm("cvt.rna.tf32.f32 %0, %1;" : "=r"(u) : "f"(x));
    return u;
}

// D += A(16x8,row) * B(8x8,col); tf32 inputs, f32 accumulate.
__device__ __forceinline__ void mma8(float d[4], const unsigned a[4], const unsigned b[2]) {
    asm volatile(
        "mma.sync.aligned.m16n8k8.row.col.f32.tf32.tf32.f32 "
        "{%0,%1,%2,%3}, {%4,%5,%6,%7}, {%8,%9}, {%0,%1,%2,%3};\n"
        : "+f"(d[0]), "+f"(d[1]), "+f"(d[2]), "+f"(d[3])
        : "r"(a[0]), "r"(a[1]), "r"(a[2]), "r"(a[3]),
          "r"(b[0]), "r"(b[1]));
}

// ---------------------------------------------------------------------------
// tf32 GEMM + bias: C[M,1024] = A[M,1024] * B[1024,1024] + bias
// 128x128 block, BK=16, 256 threads (8 warps, 2x4), warp tile 64x32.
// As[m][k] stride 20 (bank = 20g+t4, all distinct mod 32)
// Bs[k][n] stride 136 (bank = 8t4+g, all distinct mod 32)
// ---------------------------------------------------------------------------
#define AST 20
#define BST 136

__global__ __launch_bounds__(256, 2)
void sgemm_tf32_kernel(const float* __restrict__ A, const float* __restrict__ B,
                       const float* __restrict__ bias, float* __restrict__ C)
{
    const int K = 1024, N = 1024;
    __shared__ unsigned As[128 * AST];
    __shared__ unsigned Bs[16 * BST];

    const int t  = threadIdx.x;
    const int bm = blockIdx.y * 128, bn = blockIdx.x * 128;
    const int l  = t & 31, g = l >> 2, t4 = l & 3;
    const int w  = t >> 5, wm = w >> 2, wn = w & 3;   // 2 x 4 warp grid

    const int arow = t >> 1,  acol = (t & 1) * 8;     // A: 128 rows x 16 cols
    const int brow = t >> 4,  bcol = (t & 15) * 8;    // B: 16 rows x 128 cols

    float acc[4][4][4];
#pragma unroll
    for (int mi = 0; mi < 4; mi++)
#pragma unroll
        for (int ni = 0; ni < 4; ni++)
#pragma unroll
            for (int r = 0; r < 4; r++) acc[mi][ni][r] = 0.f;

    const float* Ap = A + (size_t)(bm + arow) * K + acol;
    const float* Bp = B + (size_t)brow * N + bn + bcol;

    for (int k0 = 0; k0 < K; k0 += 16) {
        float4 av0 = *(const float4*)(Ap + k0);
        float4 av1 = *(const float4*)(Ap + k0 + 4);
        float4 bv0 = *(const float4*)(Bp + (size_t)k0 * N);
        float4 bv1 = *(const float4*)(Bp + (size_t)k0 * N + 4);
        __syncthreads();
        *(uint4*)&As[arow * AST + acol]     = make_uint4(f2tf(av0.x), f2tf(av0.y), f2tf(av0.z), f2tf(av0.w));
        *(uint4*)&As[arow * AST + acol + 4] = make_uint4(f2tf(av1.x), f2tf(av1.y), f2tf(av1.z), f2tf(av1.w));
        *(uint4*)&Bs[brow * BST + bcol]     = make_uint4(f2tf(bv0.x), f2tf(bv0.y), f2tf(bv0.z), f2tf(bv0.w));
        *(uint4*)&Bs[brow * BST + bcol + 4] = make_uint4(f2tf(bv1.x), f2tf(bv1.y), f2tf(bv1.z), f2tf(bv1.w));
        __syncthreads();

#pragma unroll
        for (int kc = 0; kc < 16; kc += 8) {
            unsigned a[4][4], b[4][2];
#pragma unroll
            for (int mi = 0; mi < 4; mi++) {
                int rm = wm * 64 + mi * 16;
                a[mi][0] = As[(rm + g)     * AST + kc + t4];
                a[mi][1] = As[(rm + g + 8) * AST + kc + t4];
                a[mi][2] = As[(rm + g)     * AST + kc + t4 + 4];
                a[mi][3] = As[(rm + g + 8) * AST + kc + t4 + 4];
            }
#pragma unroll
            for (int ni = 0; ni < 4; ni++) {
                int cn = wn * 32 + ni * 8;
                b[ni][0] = Bs[(kc + t4)     * BST + cn + g];
                b[ni][1] = Bs[(kc + t4 + 4) * BST + cn + g];
            }
#pragma unroll
            for (int mi = 0; mi < 4; mi++)
#pragma unroll
                for (int ni = 0; ni < 4; ni++)
                    mma8(acc[mi][ni], a[mi], b[ni]);
        }
    }

#pragma unroll
    for (int mi = 0; mi < 4; mi++) {
        int r0 = bm + wm * 64 + mi * 16 + g;
#pragma unroll
        for (int ni = 0; ni < 4; ni++) {
            int c = bn + wn * 32 + ni * 8 + 2 * t4;
            float b0 = bias[c], b1 = bias[c + 1];
            *(float2*)&C[(size_t)r0 * N + c] =
                make_float2(acc[mi][ni][0] + b0, acc[mi][ni][1] + b1);
            *(float2*)&C[(size_t)(r0 + 8) * N + c] =
                make_float2(acc[mi][ni][2] + b0, acc[mi][ni][3] + b1);
        }
    }
}

// ---------------------------------------------------------------------------
// Flash attention, tf32 mma. Block = (b,h) x 64 query rows. Br=Bc=64, Hd=64.
// 256 threads, 8 warps (4 m-tiles x 2 n-tiles), warp tile 16x32.
// Layouts (all native row-major, conflict-free fragment reads):
//   Qs[i][d] stride 68, Ks[j][d] stride 68 (bank 4g+t4, distinct)
//   Vs[j][d] stride 72 (bank 8t4+g, distinct)
//   Ss[q][k] stride 68 (mma reads + 4-lane/row softmax both conflict-free)
// ---------------------------------------------------------------------------
#define QST 68
#define KST 68
#define VST 72
#define SST 68
#define FL_K (64 * QST)
#define FL_V (FL_K + 64 * KST)
#define FL_S (FL_V + 64 * VST)
#define FL_M (FL_S + 64 * SST)
#define FL_FLOATS (FL_M + 3 * 64)
#define FL_BYTES  (FL_FLOATS * 4)

__global__ __launch_bounds__(256, 2)
void flash_tf32_kernel(const float* __restrict__ Q, const float* __restrict__ Kg,
                       const float* __restrict__ Vg, float* __restrict__ O)
{
    extern __shared__ unsigned sm[];
    unsigned* Qs = sm;
    unsigned* Ks = sm + FL_K;
    unsigned* Vs = sm + FL_V;
    unsigned* Ss = sm + FL_S;
    float* m_s  = (float*)(sm + FL_M);
    float* l_s  = m_s + 64;
    float* al_s = l_s + 64;

    const int t  = threadIdx.x;
    const int l  = t & 31, g = l >> 2, t4 = l & 3;
    const int w  = t >> 5, wm = w & 3, wn = w >> 1 >> 1 >> 0;  // wn = w>>2
    const int wn2 = w >> 2;
    const int q0 = wm * 16, c0 = wn2 * 32;
    (void)wn;

    const int qb = blockIdx.x * 64;
    const int bh = blockIdx.y, b = bh >> 4, h = bh & 15;
    const float scale = 0.125f;   // 1/sqrt(64)

    // Load Q tile (native layout, cvt to tf32)
    const float* Qb = Q + (size_t)(b * SEQ + qb) * DMODEL + h * HDIM;
#pragma unroll
    for (int e = t * 4; e < 64 * 64; e += 1024) {
        int i = e >> 6, d = e & 63;
        float4 v = *(const float4*)&Qb[i * DMODEL + d];
        *(uint4*)&Qs[i * QST + d] = make_uint4(f2tf(v.x), f2tf(v.y), f2tf(v.z), f2tf(v.w));
    }
    if (t < 64) { m_s[t] = -1e30f; l_s[t] = 0.f; }

    float o[4][4];
#pragma unroll
    for (int ni = 0; ni < 4; ni++)
#pragma unroll
        for (int r = 0; r < 4; r++) o[ni][r] = 0.f;

    for (int kb = 0; kb < SEQ; kb += 64) {
        __syncthreads();
        const float* Kb = Kg + (size_t)(b * SEQ + kb) * DMODEL + h * HDIM;
        const float* Vb = Vg + (size_t)(b * SEQ + kb) * DMODEL + h * HDIM;
#pragma unroll
        for (int e = t * 4; e < 64 * 64; e += 1024) {
            int j = e >> 6, d = e & 63;
            float4 v = *(const float4*)&Kb[j * DMODEL + d];
            *(uint4*)&Ks[j * KST + d] = make_uint4(f2tf(v.x), f2tf(v.y), f2tf(v.z), f2tf(v.w));
            float4 u = *(const float4*)&Vb[j * DMODEL + d];
            *(uint4*)&Vs[j * VST + d] = make_uint4(f2tf(u.x), f2tf(u.y), f2tf(u.z), f2tf(u.w));
        }
        __syncthreads();

        // S = Q * K^T
        float s[4][4];
#pragma unroll
        for (int ni = 0; ni < 4; ni++)
#pragma unroll
            for (int r = 0; r < 4; r++) s[ni][r] = 0.f;
#pragma unroll
        for (int kc = 0; kc < 64; kc += 8) {
            unsigned a[4];
            a[0] = Qs[(q0 + g)     * QST + kc + t4];
            a[1] = Qs[(q0 + g + 8) * QST + kc + t4];
            a[2] = Qs[(q0 + g)     * QST + kc + t4 + 4];
            a[3] = Qs[(q0 + g + 8) * QST + kc + t4 + 4];
#pragma unroll
            for (int ni = 0; ni < 4; ni++) {
                unsigned bb[2];
                bb[0] = Ks[(c0 + ni * 8 + g) * KST + kc + t4];
                bb[1] = Ks[(c0 + ni * 8 + g) * KST + kc + t4 + 4];
                mma8(s[ni], a, bb);
            }
        }
        // Store scaled scores (fp32 bits)
#pragma unroll
        for (int ni = 0; ni < 4; ni++) {
            int c = c0 + ni * 8 + 2 * t4;
            *(uint2*)&Ss[(q0 + g) * SST + c] =
                make_uint2(__float_as_uint(s[ni][0] * scale), __float_as_uint(s[ni][1] * scale));
            *(uint2*)&Ss[(q0 + g + 8) * SST + c] =
                make_uint2(__float_as_uint(s[ni][2] * scale), __float_as_uint(s[ni][3] * scale));
        }
        __syncthreads();

        // Online softmax: 4 lanes per row (row = t>>2), conflict-free strided scan.
        {
            int r = t >> 2;
            unsigned* row = Ss + r * SST;
            float mo = m_s[r];
            float pv[16];
            float mn = mo;
#pragma unroll
            for (int jj = 0; jj < 16; jj++) {
                float x = __uint_as_float(row[t4 + jj * 4]);
                pv[jj] = x;
                mn = fmaxf(mn, x);
            }
            mn = fmaxf(mn, __shfl_xor_sync(0xffffffffu, mn, 1));
            mn = fmaxf(mn, __shfl_xor_sync(0xffffffffu, mn, 2));
            float ls = 0.f;
#pragma unroll
            for (int jj = 0; jj < 16; jj++) {
                float p = __expf(pv[jj] - mn);
                ls += p;
                row[t4 + jj * 4] = f2tf(p);   // write P as tf32 for PV mma
            }
            ls += __shfl_xor_sync(0xffffffffu, ls, 1);
            ls += __shfl_xor_sync(0xffffffffu, ls, 2);
            if (t4 == 0) {
                float al = __expf(mo - mn);
                m_s[r]  = mn;
                l_s[r]  = l_s[r] * al + ls;
                al_s[r] = al;
            }
        }
        __syncthreads();

        // Rescale O, then O += P * V
        float al0 = al_s[q0 + g], al1 = al_s[q0 + g + 8];
#pragma unroll
        for (int ni = 0; ni < 4; ni++) {
            o[ni][0] *= al0; o[ni][1] *= al0;
            o[ni][2] *= al1; o[ni][3] *= al1;
        }
#pragma unroll
        for (int kc = 0; kc < 64; kc += 8) {
            unsigned a[4];
            a[0] = Ss[(q0 + g)     * SST + kc + t4];
            a[1] = Ss[(q0 + g + 8) * SST + kc + t4];
            a[2] = Ss[(q0 + g)     * SST + kc + t4 + 4];
            a[3] = Ss[(q0 + g + 8) * SST + kc + t4 + 4];
#pragma unroll
            for (int ni = 0; ni < 4; ni++) {
                unsigned bb[2];
                bb[0] = Vs[(kc + t4)     * VST + c0 + ni * 8 + g];
                bb[1] = Vs[(kc + t4 + 4) * VST + c0 + ni * 8 + g];
                mma8(o[ni], a, bb);
            }
        }
    }

    // Epilogue: normalize and store heads
    float inv0 = 1.f / l_s[q0 + g], inv1 = 1.f / l_s[q0 + g + 8];
    float* Ob = O + (size_t)(b * SEQ + qb) * DMODEL + h * HDIM;
#pragma unroll
    for (int ni = 0; ni < 4; ni++) {
        int c = c0 + ni * 8 + 2 * t4;
        *(float2*)&Ob[(q0 + g) * DMODEL + c]     = make_float2(o[ni][0] * inv0, o[ni][1] * inv0);
        *(float2*)&Ob[(q0 + g + 8) * DMODEL + c] = make_float2(o[ni][2] * inv1, o[ni][3] * inv1);
    }
}

// ---------------------------------------------------------------------------
extern "C" void kernel_launch(void* const* d_in, const int* in_sizes, int n_in,
                              void* d_out, int out_size)
{
    (void)in_sizes; (void)n_in; (void)out_size;
    const float* x  = (const float*)d_in[0];
    const float* Wq = (const float*)d_in[1];
    const float* bq = (const float*)d_in[2];
    const float* Wk = (const float*)d_in[3];
    const float* bk = (const float*)d_in[4];
    const float* Wv = (const float*)d_in[5];
    const float* bv = (const float*)d_in[6];
    const float* Wo = (const float*)d_in[7];
    const float* bo = (const float*)d_in[8];
    float* out = (float*)d_out;

    float *gq, *gk, *gv, *gh;
    cudaGetSymbolAddress((void**)&gq, g_q);
    cudaGetSymbolAddress((void**)&gk, g_k);
    cudaGetSymbolAddress((void**)&gv, g_v);
    cudaGetSymbolAddress((void**)&gh, g_h);

    dim3 ggrid(DMODEL / 128, MROWS / 128);   // (8, 64)
    sgemm_tf32_kernel<<<ggrid, 256>>>(x, Wq, bq, gq);
    sgemm_tf32_kernel<<<ggrid, 256>>>(x, Wk, bk, gk);
    sgemm_tf32_kernel<<<ggrid, 256>>>(x, Wv, bv, gv);

    cudaFuncSetAttribute(flash_tf32_kernel,
                         cudaFuncAttributeMaxDynamicSharedMemorySize,
                         FL_BYTES);
    flash_tf32_kernel<<<dim3(SEQ / 64, BATCH * NHEADS), 256, FL_BYTES>>>(
        gq, gk, gv, gh);

    sgemm_tf32_kernel<<<ggrid, 256>>>(gh, Wo, bo, out);
}

// round 17
// speedup vs baseline: 6.5370x; 1.5069x over previous
#include <cuda_runtime.h>
#include <cuda_bf16.h>

#define BATCH   4
#define SEQ     2048
#define DMODEL  1024
#define NHEADS  16
#define HDIM    64
#define MROWS   8192
#define ELEMS   (MROWS * DMODEL)

__device__ float g_q[ELEMS];
__device__ float g_k[ELEMS];
__device__ float g_v[ELEMS];
__device__ float g_h[ELEMS];

// ---------------------------------------------------------------------------
// helpers
// ---------------------------------------------------------------------------
__device__ __forceinline__ unsigned f2tf(float x) {
    unsigned u;
    asm("cvt.rna.tf32.f32 %0, %1;" : "=r"(u) : "f"(x));
    return u;
}

__device__ __forceinline__ void mma8(float d[4], const unsigned a[4], const unsigned b[2]) {
    asm volatile(
        "mma.sync.aligned.m16n8k8.row.col.f32.tf32.tf32.f32 "
        "{%0,%1,%2,%3}, {%4,%5,%6,%7}, {%8,%9}, {%0,%1,%2,%3};\n"
        : "+f"(d[0]), "+f"(d[1]), "+f"(d[2]), "+f"(d[3])
        : "r"(a[0]), "r"(a[1]), "r"(a[2]), "r"(a[3]),
          "r"(b[0]), "r"(b[1]));
}

__device__ __forceinline__ unsigned smem_u32(const void* p) {
    unsigned r;
    asm("{ .reg .u64 t; cvta.to.shared.u64 t, %1; cvt.u32.u64 %0, t; }"
        : "=r"(r) : "l"(p));
    return r;
}
__device__ __forceinline__ void cpa16(unsigned dst, const void* src) {
    asm volatile("cp.async.cg.shared.global [%0], [%1], 16;" :: "r"(dst), "l"(src));
}
#define CP_COMMIT() asm volatile("cp.async.commit_group;" ::: "memory")
#define CP_WAIT1()  asm volatile("cp.async.wait_group 1;" ::: "memory")

// ---------------------------------------------------------------------------
// Fused QKV GEMM (z-indexed weights): C[M,1024] = A[M,1024]*B + bias
// 128x128 block, BK=16, 256 threads (8 warps 2x4), warp tile 64x32.
// 2-stage cp.async pipeline; smem holds raw fp32, cvt at fragment load.
// As[m][k] stride 20, Bs[k][n] stride 136 (conflict-free fragment reads).
// ---------------------------------------------------------------------------
#define AST 20
#define BST 136
#define GSTAGE (128 * AST + 16 * BST)   // 4736 words / stage

__global__ __launch_bounds__(256, 2)
void qkv_gemm_kernel(const float* __restrict__ A,
    const float* __restrict__ W0, const float* __restrict__ bias0, float* __restrict__ C0,
    const float* __restrict__ W1, const float* __restrict__ bias1, float* __restrict__ C1,
    const float* __restrict__ W2, const float* __restrict__ bias2, float* __restrict__ C2)
{
    const int K = 1024, N = 1024;
    __shared__ float smg[2 * GSTAGE];

    const float* B    = W0;
    const float* bias = bias0;
    float*       C    = C0;
    if (blockIdx.z == 1) { B = W1; bias = bias1; C = C1; }
    else if (blockIdx.z == 2) { B = W2; bias = bias2; C = C2; }

    const int t  = threadIdx.x;
    const int bm = blockIdx.y * 128, bn = blockIdx.x * 128;
    const int l  = t & 31, g = l >> 2, t4 = l & 3;
    const int w  = t >> 5, wm = w >> 2, wn = w & 3;

    const int arow = t >> 1,  acol = (t & 1) * 8;
    const int brow = t >> 4,  bcol = (t & 15) * 8;

    const float* Ap = A + (size_t)(bm + arow) * K + acol;
    const float* Bp = B + (size_t)brow * N + bn + bcol;

    const unsigned base = smem_u32(smg);
    unsigned sA[2], sB[2];
#pragma unroll
    for (int s = 0; s < 2; s++) {
        sA[s] = base + (s * GSTAGE + arow * AST + acol) * 4;
        sB[s] = base + (s * GSTAGE + 128 * AST + brow * BST + bcol) * 4;
    }

    float acc[4][4][4];
#pragma unroll
    for (int mi = 0; mi < 4; mi++)
#pragma unroll
        for (int ni = 0; ni < 4; ni++)
#pragma unroll
            for (int r = 0; r < 4; r++) acc[mi][ni][r] = 0.f;

    // prefetch tile 0
    cpa16(sA[0],      Ap);
    cpa16(sA[0] + 16, Ap + 4);
    cpa16(sB[0],      Bp);
    cpa16(sB[0] + 16, Bp + 4);
    CP_COMMIT();

    for (int it = 0; it < 64; it++) {
        if (it < 63) {
            int k0 = (it + 1) * 16;
            int s  = (it + 1) & 1;
            cpa16(sA[s],      Ap + k0);
            cpa16(sA[s] + 16, Ap + k0 + 4);
            cpa16(sB[s],      Bp + (size_t)k0 * N);
            cpa16(sB[s] + 16, Bp + (size_t)k0 * N + 4);
        }
        CP_COMMIT();
        CP_WAIT1();
        __syncthreads();

        const float* As = smg + (it & 1) * GSTAGE;
        const float* Bs = As + 128 * AST;

#pragma unroll
        for (int kc = 0; kc < 16; kc += 8) {
            unsigned a[4][4], b[4][2];
#pragma unroll
            for (int mi = 0; mi < 4; mi++) {
                int rm = wm * 64 + mi * 16;
                a[mi][0] = f2tf(As[(rm + g)     * AST + kc + t4]);
                a[mi][1] = f2tf(As[(rm + g + 8) * AST + kc + t4]);
                a[mi][2] = f2tf(As[(rm + g)     * AST + kc + t4 + 4]);
                a[mi][3] = f2tf(As[(rm + g + 8) * AST + kc + t4 + 4]);
            }
#pragma unroll
            for (int ni = 0; ni < 4; ni++) {
                int cn = wn * 32 + ni * 8;
                b[ni][0] = f2tf(Bs[(kc + t4)     * BST + cn + g]);
                b[ni][1] = f2tf(Bs[(kc + t4 + 4) * BST + cn + g]);
            }
#pragma unroll
            for (int mi = 0; mi < 4; mi++)
#pragma unroll
                for (int ni = 0; ni < 4; ni++)
                    mma8(acc[mi][ni], a[mi], b[ni]);
        }
        __syncthreads();
    }

#pragma unroll
    for (int mi = 0; mi < 4; mi++) {
        int r0 = bm + wm * 64 + mi * 16 + g;
#pragma unroll
        for (int ni = 0; ni < 4; ni++) {
            int c = bn + wn * 32 + ni * 8 + 2 * t4;
            float b0 = bias[c], b1 = bias[c + 1];
            *(float2*)&C[(size_t)r0 * N + c] =
                make_float2(acc[mi][ni][0] + b0, acc[mi][ni][1] + b1);
            *(float2*)&C[(size_t)(r0 + 8) * N + c] =
                make_float2(acc[mi][ni][2] + b0, acc[mi][ni][3] + b1);
        }
    }
}

// ---------------------------------------------------------------------------
// Flash attention v2: Br=128, Bc=64, Hd=64. 128 threads (4 warps), warp tile
// 32 rows x 64 cols. Softmax + P entirely in registers (quad shuffles);
// P->A-fragment rearrange via lane shuffles. K/V double-buffered via cp.async.
//   Qs[i][d] stride 68 (pre-converted tf32, pre-scaled by 1/8)
//   Ks[j][d] stride 68, Vs[j][d] stride 72 (raw fp32, cvt at frag load)
// ---------------------------------------------------------------------------
#define QST 68
#define KST 68
#define VST 72
#define FQ      (128 * QST)              // 8704 words
#define KVSTAGE (64 * KST + 64 * VST)    // 8960 words
#define FL_BYTES ((FQ + 2 * KVSTAGE) * 4)  // 106496 B

__global__ __launch_bounds__(128, 2)
void flash2_kernel(const float* __restrict__ Q, const float* __restrict__ Kg,
                   const float* __restrict__ Vg, float* __restrict__ O)
{
    extern __shared__ float sm[];
    float* Qs = sm;

    const int t  = threadIdx.x;
    const int l  = t & 31, g = l >> 2, t4 = l & 3;
    const int w  = t >> 5;
    const int q0 = w * 32;

    const int qb = blockIdx.x * 128;
    const int bh = blockIdx.y, b = bh >> 4, h = bh & 15;

    const unsigned sbase = smem_u32(sm);

    // Stage Q (tf32, pre-scaled by 1/sqrt(64) = 0.125 exactly)
    const float* Qb = Q + (size_t)(b * SEQ + qb) * DMODEL + h * HDIM;
#pragma unroll
    for (int e = t * 4; e < 128 * 64; e += 512) {
        int i = e >> 6, d = e & 63;
        float4 v = *(const float4*)&Qb[(size_t)i * DMODEL + d];
        Qs[i * QST + d + 0] = __uint_as_float(f2tf(v.x * 0.125f));
        Qs[i * QST + d + 1] = __uint_as_float(f2tf(v.y * 0.125f));
        Qs[i * QST + d + 2] = __uint_as_float(f2tf(v.z * 0.125f));
        Qs[i * QST + d + 3] = __uint_as_float(f2tf(v.w * 0.125f));
    }

    const float* Kbh = Kg + (size_t)(b * SEQ) * DMODEL + h * HDIM;
    const float* Vbh = Vg + (size_t)(b * SEQ) * DMODEL + h * HDIM;

    // prefetch KV tile 0 into stage 0
    {
        unsigned ks = sbase + FQ * 4;
        unsigned vs = ks + 64 * KST * 4;
#pragma unroll
        for (int e = t * 4; e < 64 * 64; e += 512) {
            int j = e >> 6, d = e & 63;
            cpa16(ks + (j * KST + d) * 4, Kbh + (size_t)j * DMODEL + d);
            cpa16(vs + (j * VST + d) * 4, Vbh + (size_t)j * DMODEL + d);
        }
    }
    CP_COMMIT();

    float o[2][8][4];
#pragma unroll
    for (int mi = 0; mi < 2; mi++)
#pragma unroll
        for (int ni = 0; ni < 8; ni++)
#pragma unroll
            for (int r = 0; r < 4; r++) o[mi][ni][r] = 0.f;
    float mrow[4] = {-1e30f, -1e30f, -1e30f, -1e30f};   // rows: mi*16+{g, g+8}
    float lrow[4] = {0.f, 0.f, 0.f, 0.f};

    const int laneA = (l & ~3) | (t4 >> 1);
    const int laneB = laneA | 2;
    const bool oddk = (t4 & 1);

    for (int it = 0; it < SEQ / 64; it++) {
        if (it < SEQ / 64 - 1) {
            int kb = (it + 1) * 64;
            unsigned ks = sbase + (FQ + ((it + 1) & 1) * KVSTAGE) * 4;
            unsigned vs = ks + 64 * KST * 4;
#pragma unroll
            for (int e = t * 4; e < 64 * 64; e += 512) {
                int j = e >> 6, d = e & 63;
                cpa16(ks + (j * KST + d) * 4, Kbh + (size_t)(kb + j) * DMODEL + d);
                cpa16(vs + (j * VST + d) * 4, Vbh + (size_t)(kb + j) * DMODEL + d);
            }
        }
        CP_COMMIT();
        CP_WAIT1();
        __syncthreads();

        const float* Ks = sm + FQ + (it & 1) * KVSTAGE;
        const float* Vs = Ks + 64 * KST;

        // ---- S = (Q*scale) * K^T ----
        float s[2][8][4];
#pragma unroll
        for (int mi = 0; mi < 2; mi++)
#pragma unroll
            for (int ni = 0; ni < 8; ni++)
#pragma unroll
                for (int r = 0; r < 4; r++) s[mi][ni][r] = 0.f;

#pragma unroll
        for (int kc = 0; kc < 64; kc += 8) {
            unsigned a[2][4];
#pragma unroll
            for (int mi = 0; mi < 2; mi++) {
                int rm = q0 + mi * 16;
                a[mi][0] = __float_as_uint(Qs[(rm + g)     * QST + kc + t4]);
                a[mi][1] = __float_as_uint(Qs[(rm + g + 8) * QST + kc + t4]);
                a[mi][2] = __float_as_uint(Qs[(rm + g)     * QST + kc + t4 + 4]);
                a[mi][3] = __float_as_uint(Qs[(rm + g + 8) * QST + kc + t4 + 4]);
            }
#pragma unroll
            for (int ni = 0; ni < 8; ni++) {
                unsigned bb[2];
                bb[0] = f2tf(Ks[(ni * 8 + g) * KST + kc + t4]);
                bb[1] = f2tf(Ks[(ni * 8 + g) * KST + kc + t4 + 4]);
                mma8(s[0][ni], a[0], bb);
                mma8(s[1][ni], a[1], bb);
            }
        }

        // ---- online softmax in registers (rows live in one warp's quads) ----
#pragma unroll
        for (int mi = 0; mi < 2; mi++) {
            float mA = -1e30f, mB = -1e30f;
#pragma unroll
            for (int ni = 0; ni < 8; ni++) {
                mA = fmaxf(mA, fmaxf(s[mi][ni][0], s[mi][ni][1]));
                mB = fmaxf(mB, fmaxf(s[mi][ni][2], s[mi][ni][3]));
            }
            mA = fmaxf(mA, __shfl_xor_sync(0xffffffffu, mA, 1));
            mA = fmaxf(mA, __shfl_xor_sync(0xffffffffu, mA, 2));
            mB = fmaxf(mB, __shfl_xor_sync(0xffffffffu, mB, 1));
            mB = fmaxf(mB, __shfl_xor_sync(0xffffffffu, mB, 2));

            float moA = mrow[mi * 2], moB = mrow[mi * 2 + 1];
            float mnA = fmaxf(moA, mA), mnB = fmaxf(moB, mB);
            float alA = __expf(moA - mnA), alB = __expf(moB - mnB);
            mrow[mi * 2]     = mnA;
            mrow[mi * 2 + 1] = mnB;

            float sumA = 0.f, sumB = 0.f;
#pragma unroll
            for (int ni = 0; ni < 8; ni++) {
                float p0 = __expf(s[mi][ni][0] - mnA);
                float p1 = __expf(s[mi][ni][1] - mnA);
                float p2 = __expf(s[mi][ni][2] - mnB);
                float p3 = __expf(s[mi][ni][3] - mnB);
                s[mi][ni][0] = p0; s[mi][ni][1] = p1;
                s[mi][ni][2] = p2; s[mi][ni][3] = p3;
                sumA += p0 + p1;
                sumB += p2 + p3;
            }
            sumA += __shfl_xor_sync(0xffffffffu, sumA, 1);
            sumA += __shfl_xor_sync(0xffffffffu, sumA, 2);
            sumB += __shfl_xor_sync(0xffffffffu, sumB, 1);
            sumB += __shfl_xor_sync(0xffffffffu, sumB, 2);
            lrow[mi * 2]     = lrow[mi * 2]     * alA + sumA;
            lrow[mi * 2 + 1] = lrow[mi * 2 + 1] * alB + sumB;

#pragma unroll
            for (int ni = 0; ni < 8; ni++) {
                o[mi][ni][0] *= alA; o[mi][ni][1] *= alA;
                o[mi][ni][2] *= alB; o[mi][ni][3] *= alB;
            }
        }

        // ---- O += P * V  (P rearranged acc->A-frag via quad shuffles) ----
#pragma unroll
        for (int ks8 = 0; ks8 < 8; ks8++) {
            unsigned pa[2][4];
#pragma unroll
            for (int mi = 0; mi < 2; mi++) {
                float x0 = __shfl_sync(0xffffffffu, s[mi][ks8][0], laneA);
                float x1 = __shfl_sync(0xffffffffu, s[mi][ks8][1], laneA);
                float x2 = __shfl_sync(0xffffffffu, s[mi][ks8][2], laneA);
                float x3 = __shfl_sync(0xffffffffu, s[mi][ks8][3], laneA);
                float y0 = __shfl_sync(0xffffffffu, s[mi][ks8][0], laneB);
                float y1 = __shfl_sync(0xffffffffu, s[mi][ks8][1], laneB);
                float y2 = __shfl_sync(0xffffffffu, s[mi][ks8][2], laneB);
                float y3 = __shfl_sync(0xffffffffu, s[mi][ks8][3], laneB);
                pa[mi][0] = f2tf(oddk ? x1 : x0);
                pa[mi][1] = f2tf(oddk ? x3 : x2);
                pa[mi][2] = f2tf(oddk ? y1 : y0);
                pa[mi][3] = f2tf(oddk ? y3 : y2);
            }
#pragma unroll
            for (int ni = 0; ni < 8; ni++) {
                unsigned bb[2];
                bb[0] = f2tf(Vs[(ks8 * 8 + t4)     * VST + ni * 8 + g]);
                bb[1] = f2tf(Vs[(ks8 * 8 + t4 + 4) * VST + ni * 8 + g]);
                mma8(o[0][ni], pa[0], bb);
                mma8(o[1][ni], pa[1], bb);
            }
        }
        __syncthreads();
    }

    // ---- epilogue: normalize, store heads ----
    float* Ob = O + (size_t)(b * SEQ + qb) * DMODEL + h * HDIM;
#pragma unroll
    for (int mi = 0; mi < 2; mi++) {
        float invA = 1.f / lrow[mi * 2];
        float invB = 1.f / lrow[mi * 2 + 1];
        int rA = q0 + mi * 16 + g;
#pragma unroll
        for (int ni = 0; ni < 8; ni++) {
            int c = ni * 8 + 2 * t4;
            *(float2*)&Ob[(size_t)rA * DMODEL + c] =
                make_float2(o[mi][ni][0] * invA, o[mi][ni][1] * invA);
            *(float2*)&Ob[(size_t)(rA + 8) * DMODEL + c] =
                make_float2(o[mi][ni][2] * invB, o[mi][ni][3] * invB);
        }
    }
}

// ---------------------------------------------------------------------------
extern "C" void kernel_launch(void* const* d_in, const int* in_sizes, int n_in,
                              void* d_out, int out_size)
{
    (void)in_sizes; (void)n_in; (void)out_size;
    const float* x  = (const float*)d_in[0];
    const float* Wq = (const float*)d_in[1];
    const float* bq = (const float*)d_in[2];
    const float* Wk = (const float*)d_in[3];
    const float* bk = (const float*)d_in[4];
    const float* Wv = (const float*)d_in[5];
    const float* bv = (const float*)d_in[6];
    const float* Wo = (const float*)d_in[7];
    const float* bo = (const float*)d_in[8];
    float* out = (float*)d_out;

    float *gq, *gk, *gv, *gh;
    cudaGetSymbolAddress((void**)&gq, g_q);
    cudaGetSymbolAddress((void**)&gk, g_k);
    cudaGetSymbolAddress((void**)&gv, g_v);
    cudaGetSymbolAddress((void**)&gh, g_h);

    // Fused QKV projections: grid z selects (W, b, C)
    qkv_gemm_kernel<<<dim3(DMODEL / 128, MROWS / 128, 3), 256>>>(
        x, Wq, bq, gq, Wk, bk, gk, Wv, bv, gv);

    cudaFuncSetAttribute(flash2_kernel,
                         cudaFuncAttributeMaxDynamicSharedMemorySize, FL_BYTES);
    flash2_kernel<<<dim3(SEQ / 128, BATCH * NHEADS), 128, FL_BYTES>>>(
        gq, gk, gv, gh);

    // Output projection (z = 0 only)
    qkv_gemm_kernel<<<dim3(DMODEL / 128, MROWS / 128, 1), 256>>>(
        gh, Wo, bo, out, Wo, bo, out, Wo, bo, out);
}